// round 6
// baseline (speedup 1.0000x reference)
#include <cuda_runtime.h>
#include <cstdint>

#define Np   262144
#define Bn   4
#define Hn   512
#define Wn   512
#define NINS 16
#define EPSF 1e-5f

// ---------------- device scratch ----------------
__device__ int   g_idx_map[Bn * Hn * Wn];
__device__ float g_h[3u * Np * 64u];
__device__ float g_sum [3 * NINS * 64];
__device__ float g_sum2[3 * NINS * 64];
__device__ float g_mean[3 * NINS * 64];
__device__ float g_rinv[3 * NINS * 64];
__device__ int   g_cnt [NINS];
__device__ int   g_ymin[NINS], g_ymax[NINS], g_xmin[NINS], g_xmax[NINS];
__device__ int   g_dil[3 * NINS];
// prepped weights: [br][tap][s][col][j], j = tig*2+h, k = s*8+tig+4h
__device__ float g_wtb[3 * 9 * 8 * 64 * 8];     // 110592
// final: [u=tap*4+c][s][col][j], k = c*64 + s*8+tig+4h
__device__ float g_wtf2[36 * 8 * 64 * 8];       // 147456

// ---------------- helpers ----------------
__device__ __forceinline__ float tf32r(float x) {
    uint32_t u;
    asm("cvt.rna.tf32.f32 %0, %1;" : "=r"(u) : "f"(x));
    return __uint_as_float(u);
}

__device__ __forceinline__ void mma_tf32(float* d, const float* a, const float* b) {
    uint32_t a0 = __float_as_uint(a[0]), a1 = __float_as_uint(a[1]);
    uint32_t a2 = __float_as_uint(a[2]), a3 = __float_as_uint(a[3]);
    uint32_t b0 = __float_as_uint(b[0]), b1 = __float_as_uint(b[1]);
    asm volatile(
        "mma.sync.aligned.m16n8k8.row.col.f32.tf32.tf32.f32 "
        "{%0,%1,%2,%3}, {%4,%5,%6,%7}, {%8,%9}, {%0,%1,%2,%3};"
        : "+f"(d[0]), "+f"(d[1]), "+f"(d[2]), "+f"(d[3])
        : "r"(a0), "r"(a1), "r"(a2), "r"(a3), "r"(b0), "r"(b1));
}

#define APAD 68
#define SA_ELEMS (128 * APAD)
#define SB_FLOATS 4096

// ---------------- init / scatter / dil (proven) ----------------
__global__ void k_init() {
    int i = blockIdx.x * blockDim.x + threadIdx.x;
    if (i < Bn * Hn * Wn) g_idx_map[i] = -1;
    if (i < 3 * NINS * 64) { g_sum[i] = 0.f; g_sum2[i] = 0.f; }
    if (i < NINS) {
        g_cnt[i] = 0;
        g_ymin[i] = 0x7FFFFFFF; g_ymax[i] = 0x80000000;
        g_xmin[i] = 0x7FFFFFFF; g_xmax[i] = 0x80000000;
    }
}

__global__ void k_scatter(const int* __restrict__ idxs, const int* __restrict__ seg) {
    __shared__ int sy0[NINS], sy1[NINS], sx0[NINS], sx1[NINS], sc[NINS];
    int tid = threadIdx.x;
    if (tid < NINS) { sy0[tid] = 0x7FFFFFFF; sy1[tid] = 0x80000000;
                      sx0[tid] = 0x7FFFFFFF; sx1[tid] = 0x80000000; sc[tid] = 0; }
    __syncthreads();
    int i = blockIdx.x * blockDim.x + tid;
    if (i < Np) {
        int b = idxs[3*i], y = idxs[3*i+1], x = idxs[3*i+2];
        g_idx_map[(b * Hn + y) * Wn + x] = i;
        int s = seg[i];
        atomicMin(&sy0[s], y); atomicMax(&sy1[s], y);
        atomicMin(&sx0[s], x); atomicMax(&sx1[s], x);
        atomicAdd(&sc[s], 1);
    }
    __syncthreads();
    if (tid < NINS && sc[tid] > 0) {
        atomicMin(&g_ymin[tid], sy0[tid]); atomicMax(&g_ymax[tid], sy1[tid]);
        atomicMin(&g_xmin[tid], sx0[tid]); atomicMax(&g_xmax[tid], sx1[tid]);
        atomicAdd(&g_cnt[tid], sc[tid]);
    }
}

__global__ void k_dil() {
    int i = threadIdx.x;
    if (i < 3 * NINS) {
        int s = i & 15, r = i >> 4;
        int rate = (r == 0) ? 1 : (r == 1) ? 3 : 5;
        float hr = (float)(g_ymax[s] - g_ymin[s]) / (float)Hn;
        float wr = (float)(g_xmax[s] - g_xmin[s]) / (float)Wn;
        int d = (int)ceilf(fmaxf(hr, wr) * (float)rate);
        if (d < 1) d = 1;
        g_dil[r * NINS + s] = d;
    }
}

// ---------------- weight prep: transpose + tf32 + fragment permute --------
__global__ void k_prepw(const float* __restrict__ w1, const float* __restrict__ w2,
                        const float* __restrict__ w3, const float* __restrict__ wf)
{
    int i = blockIdx.x * blockDim.x + threadIdx.x;
    if (i < 110592) {
        int br  = i / 36864;
        int r   = i % 36864;
        int tap = r / 4096;
        int r2  = r % 4096;
        int s   = r2 >> 9;
        int col = (r2 >> 3) & 63;
        int j   = r2 & 7;
        int k   = s * 8 + (j >> 1) + 4 * (j & 1);
        const float* w = (br == 0) ? w1 : (br == 1) ? w2 : w3;
        g_wtb[i] = tf32r(w[tap * 4096 + k * 64 + col]);
    } else if (i < 110592 + 147456) {
        int i2  = i - 110592;
        int u   = i2 / 4096;
        int r2  = i2 % 4096;
        int s   = r2 >> 9;
        int col = (r2 >> 3) & 63;
        int j   = r2 & 7;
        int tap = u >> 2, c = u & 3;
        int k   = c * 64 + s * 8 + (j >> 1) + 4 * (j & 1);
        g_wtf2[i2] = tf32r(wf[((size_t)tap * 256 + k) * 64 + col]);
    }
}

// ---------------- branch conv: 4 warps, warp tile 32x64 --------------------
__global__ void __launch_bounds__(128) k_branch_mma(
    const float* __restrict__ feats, const int* __restrict__ idxs,
    const int* __restrict__ seg,
    const float* __restrict__ bias1, const float* __restrict__ bias2,
    const float* __restrict__ bias3)
{
    extern __shared__ float sm[];
    float* sA   = sm;                        // [128][68]
    float* sB2  = sm + SA_ELEMS;             // [4096] per-tap permuted B
    int*   snbr = (int*)(sm + SA_ELEMS + SB_FLOATS);

    int tid = threadIdx.x;
    int br  = blockIdx.y;
    int p0  = blockIdx.x * 128;
    const float* bias = (br == 0) ? bias1 : (br == 1) ? bias2 : bias3;

    for (int t = tid; t < 128 * 9; t += 128) {
        int p = t / 9, k = t % 9;
        int gi = p0 + p;
        int b = idxs[3*gi], y = idxs[3*gi+1], x = idxs[3*gi+2];
        int sgi = seg[gi];
        int d = g_dil[br * NINS + sgi];
        int ky = k / 3 - 1, kx = k % 3 - 1;
        int ny = y + ky * d, nx = x + kx * d;
        int nbr = -1;
        if (ny >= 0 && ny < Hn && nx >= 0 && nx < Wn) {
            int n = g_idx_map[(b * Hn + ny) * Wn + nx];
            if (n >= 0 && seg[n] == sgi) nbr = n;
        }
        snbr[t] = nbr;
    }
    __syncthreads();

    int lane = tid & 31, wid = tid >> 5;
    int gid = lane >> 2, tig = lane & 3;
    int sub = lane >> 4, li = lane & 15;

    float acc[2][8][4];
#pragma unroll
    for (int mi = 0; mi < 2; mi++)
#pragma unroll
        for (int ni = 0; ni < 8; ni++)
#pragma unroll
            for (int e = 0; e < 4; e++) acc[mi][ni][e] = 0.f;

    const float* wtb = g_wtb + (size_t)(br * 9) * 4096;

    for (int k = 0; k < 9; k++) {
        // A fill: 2 rows per warp-instr, 16 iters (32 rows per warp)
#pragma unroll
        for (int j = 0; j < 16; j++) {
            int row = wid * 32 + j * 2 + sub;
            int nbr = snbr[row * 9 + k];
            float4 f = make_float4(0.f, 0.f, 0.f, 0.f);
            if (nbr >= 0) f = ((const float4*)(feats + (size_t)nbr * 64))[li];
            f.x = tf32r(f.x); f.y = tf32r(f.y);
            f.z = tf32r(f.z); f.w = tf32r(f.w);
            *(float4*)(sA + row * APAD + li * 4) = f;
        }
        // B fill: coalesced copy of prepped tap slice (4096 floats = 1024 float4)
        {
            const float4* src = (const float4*)(wtb + k * 4096);
            float4*       dst = (float4*)sB2;
#pragma unroll
            for (int j = 0; j < 8; j++) dst[tid + 128 * j] = src[tid + 128 * j];
        }
        __syncthreads();

        const float2* sB2v = (const float2*)sB2;
#pragma unroll
        for (int s = 0; s < 8; s++) {
            float a[2][4];
#pragma unroll
            for (int mi = 0; mi < 2; mi++) {
                const float* ap = sA + (wid * 32 + mi * 16 + gid) * APAD + s * 8 + tig;
                a[mi][0] = ap[0];
                a[mi][1] = ap[8 * APAD];
                a[mi][2] = ap[4];
                a[mi][3] = ap[8 * APAD + 4];
            }
#pragma unroll
            for (int ni = 0; ni < 8; ni++) {
                float2 bb = sB2v[(s * 64 + ni * 8 + gid) * 4 + tig];
                mma_tf32(acc[0][ni], a[0], (const float*)&bb);
                mma_tf32(acc[1][ni], a[1], (const float*)&bb);
            }
        }
        __syncthreads();
    }

    float* hout = g_h + (size_t)br * Np * 64;
#pragma unroll
    for (int ni = 0; ni < 8; ni++) {
        int col = ni * 8 + tig * 2;
        float2 bb = *(const float2*)(bias + col);
#pragma unroll
        for (int mi = 0; mi < 2; mi++) {
            int row = p0 + wid * 32 + mi * 16 + gid;
            float2 v0 = make_float2(acc[mi][ni][0] + bb.x, acc[mi][ni][1] + bb.y);
            float2 v1 = make_float2(acc[mi][ni][2] + bb.x, acc[mi][ni][3] + bb.y);
            *(float2*)(hout + (size_t)row * 64 + col) = v0;
            *(float2*)(hout + (size_t)(row + 8) * 64 + col) = v1;
        }
    }
}

// ---------------- segment stats (proven) ----------------
__global__ void k_stats(const int* __restrict__ seg) {
    int br   = blockIdx.y;
    int base = blockIdx.x * 1024;
    int c  = threadIdx.x & 63;
    int rs = threadIdx.x >> 6;
    const float* h = g_h + (size_t)br * Np * 64;
    float s = 0.f, s2 = 0.f;
    int cur = seg[base + rs];
    for (int j = 0; j < 256; j++) {
        int p = base + rs + 4 * j;
        int sg = seg[p];
        if (sg != cur) {
            atomicAdd(&g_sum [(br * NINS + cur) * 64 + c], s);
            atomicAdd(&g_sum2[(br * NINS + cur) * 64 + c], s2);
            s = 0.f; s2 = 0.f; cur = sg;
        }
        float v = h[(size_t)p * 64 + c];
        s += v; s2 += v * v;
    }
    atomicAdd(&g_sum [(br * NINS + cur) * 64 + c], s);
    atomicAdd(&g_sum2[(br * NINS + cur) * 64 + c], s2);
}

__global__ void k_normfin() {
    int i = blockIdx.x * blockDim.x + threadIdx.x;
    if (i < 3 * NINS * 64) {
        int sgl = (i / 64) % NINS;
        float cnt = (float)g_cnt[sgl];
        float mean = g_sum[i] / cnt;
        float var  = g_sum2[i] / cnt - mean * mean;
        g_mean[i] = mean;
        g_rinv[i] = rsqrtf(var + EPSF);
    }
}

// ---------------- final conv: 4 warps, 36 stages ---------------------------
__global__ void __launch_bounds__(128) k_final_mma(
    const float* __restrict__ feats, const int* __restrict__ idxs,
    const int* __restrict__ seg, const float* __restrict__ bf,
    float* __restrict__ out)
{
    extern __shared__ float sm[];
    float* sA    = sm;
    float* sB2   = sm + SA_ELEMS;
    int*   snbr  = (int*)(sm + SA_ELEMS + SB_FLOATS);
    int*   snseg = snbr + 128 * 9;

    int tid = threadIdx.x;
    int p0  = blockIdx.x * 128;

    for (int t = tid; t < 128 * 9; t += 128) {
        int p = t / 9, k = t % 9;
        int gi = p0 + p;
        int b = idxs[3*gi], y = idxs[3*gi+1], x = idxs[3*gi+2];
        int ky = k / 3 - 1, kx = k % 3 - 1;
        int ny = y + ky, nx = x + kx;
        int nbr = -1, sgn = 0;
        if (ny >= 0 && ny < Hn && nx >= 0 && nx < Wn) {
            int n = g_idx_map[(b * Hn + ny) * Wn + nx];
            if (n >= 0) { nbr = n; sgn = seg[n]; }
        }
        snbr[t] = nbr; snseg[t] = sgn;
    }
    __syncthreads();

    int lane = tid & 31, wid = tid >> 5;
    int gid = lane >> 2, tig = lane & 3;
    int sub = lane >> 4, li = lane & 15;

    float acc[2][8][4];
#pragma unroll
    for (int mi = 0; mi < 2; mi++)
#pragma unroll
        for (int ni = 0; ni < 8; ni++)
#pragma unroll
            for (int e = 0; e < 4; e++) acc[mi][ni][e] = 0.f;

    for (int u = 0; u < 36; u++) {
        int k = u >> 2, c = u & 3;

        // A fill
        if (c == 0) {
#pragma unroll
            for (int j = 0; j < 16; j++) {
                int row = wid * 32 + j * 2 + sub;
                int nbr = snbr[row * 9 + k];
                float4 f = make_float4(0.f, 0.f, 0.f, 0.f);
                if (nbr >= 0) f = ((const float4*)(feats + (size_t)nbr * 64))[li];
                f.x = tf32r(f.x); f.y = tf32r(f.y);
                f.z = tf32r(f.z); f.w = tf32r(f.w);
                *(float4*)(sA + row * APAD + li * 4) = f;
            }
        } else {
            int brr = c - 1;
            const float* hbase = g_h + (size_t)brr * Np * 64;
#pragma unroll
            for (int j = 0; j < 16; j++) {
                int row = wid * 32 + j * 2 + sub;
                int nbr = snbr[row * 9 + k];
                float4 v = make_float4(0.f, 0.f, 0.f, 0.f);
                if (nbr >= 0) {
                    float4 hv = ((const float4*)(hbase + (size_t)nbr * 64))[li];
                    int tb = ((brr * NINS + snseg[row * 9 + k]) << 6) + li * 4;
                    float4 mm = *(const float4*)(g_mean + tb);
                    float4 rr = *(const float4*)(g_rinv + tb);
                    v.x = fmaxf(0.f, (hv.x - mm.x) * rr.x);
                    v.y = fmaxf(0.f, (hv.y - mm.y) * rr.y);
                    v.z = fmaxf(0.f, (hv.z - mm.z) * rr.z);
                    v.w = fmaxf(0.f, (hv.w - mm.w) * rr.w);
                }
                v.x = tf32r(v.x); v.y = tf32r(v.y);
                v.z = tf32r(v.z); v.w = tf32r(v.w);
                *(float4*)(sA + row * APAD + li * 4) = v;
            }
        }
        // B fill: 4096 floats
        {
            const float4* src = (const float4*)(g_wtf2 + u * 4096);
            float4*       dst = (float4*)sB2;
#pragma unroll
            for (int j = 0; j < 8; j++) dst[tid + 128 * j] = src[tid + 128 * j];
        }
        __syncthreads();

        const float2* sB2v = (const float2*)sB2;
#pragma unroll
        for (int s = 0; s < 8; s++) {
            float a[2][4];
#pragma unroll
            for (int mi = 0; mi < 2; mi++) {
                const float* ap = sA + (wid * 32 + mi * 16 + gid) * APAD + s * 8 + tig;
                a[mi][0] = ap[0];
                a[mi][1] = ap[8 * APAD];
                a[mi][2] = ap[4];
                a[mi][3] = ap[8 * APAD + 4];
            }
#pragma unroll
            for (int ni = 0; ni < 8; ni++) {
                float2 bb = sB2v[(s * 64 + ni * 8 + gid) * 4 + tig];
                mma_tf32(acc[0][ni], a[0], (const float*)&bb);
                mma_tf32(acc[1][ni], a[1], (const float*)&bb);
            }
        }
        __syncthreads();
    }

#pragma unroll
    for (int ni = 0; ni < 8; ni++) {
        int col = ni * 8 + tig * 2;
        float2 bb = *(const float2*)(bf + col);
#pragma unroll
        for (int mi = 0; mi < 2; mi++) {
            int row = p0 + wid * 32 + mi * 16 + gid;
            float2 v0 = make_float2(acc[mi][ni][0] + bb.x, acc[mi][ni][1] + bb.y);
            float2 v1 = make_float2(acc[mi][ni][2] + bb.x, acc[mi][ni][3] + bb.y);
            *(float2*)(out + (size_t)row * 64 + col) = v0;
            *(float2*)(out + (size_t)(row + 8) * 64 + col) = v1;
        }
    }
}

// ---------------- launch ----------------
#define SMEM_BRANCH ((SA_ELEMS + SB_FLOATS + 128 * 9) * 4)
#define SMEM_FINAL  ((SA_ELEMS + SB_FLOATS + 2 * 128 * 9) * 4)

extern "C" void kernel_launch(void* const* d_in, const int* in_sizes, int n_in,
                              void* d_out, int out_size)
{
    const float* feats = (const float*)d_in[0];
    const int*   idxs  = (const int*)  d_in[1];
    const int*   seg   = (const int*)  d_in[2];
    const float* w1    = (const float*)d_in[3];
    const float* b1    = (const float*)d_in[4];
    const float* w2    = (const float*)d_in[5];
    const float* b2    = (const float*)d_in[6];
    const float* w3    = (const float*)d_in[7];
    const float* b3    = (const float*)d_in[8];
    const float* wf    = (const float*)d_in[9];
    const float* bf    = (const float*)d_in[10];
    float* out = (float*)d_out;

    cudaFuncSetAttribute(k_branch_mma, cudaFuncAttributeMaxDynamicSharedMemorySize, SMEM_BRANCH);
    cudaFuncSetAttribute(k_final_mma,  cudaFuncAttributeMaxDynamicSharedMemorySize, SMEM_FINAL);

    k_init<<<(Bn * Hn * Wn + 255) / 256, 256>>>();
    k_scatter<<<(Np + 255) / 256, 256>>>(idxs, seg);
    k_dil<<<1, 64>>>();
    k_prepw<<<(110592 + 147456 + 255) / 256, 256>>>(w1, w2, w3, wf);

    dim3 gb(Np / 128, 3);
    k_branch_mma<<<gb, 128, SMEM_BRANCH>>>(feats, idxs, seg, b1, b2, b3);

    dim3 sg(Np / 1024, 3);
    k_stats<<<sg, 256>>>(seg);
    k_normfin<<<12, 256>>>();

    k_final_mma<<<Np / 128, 128, SMEM_FINAL>>>(feats, idxs, seg, bf, out);
}

// round 8
// speedup vs baseline: 1.3152x; 1.3152x over previous
#include <cuda_runtime.h>
#include <cuda_fp16.h>
#include <cstdint>

#define Np   262144
#define Bn   4
#define Hn   512
#define Wn   512
#define NINS 16
#define EPSF 1e-5f

// ---------------- device scratch ----------------
__device__ int   g_idx_map[Bn * Hn * Wn];
__device__ float g_h[3u * Np * 64u];              // raw branch outputs fp32
__device__ uint2 g_hn[3u * Np * 16u];             // relu(norm(h)) fp16: 16 uint2 per row
__device__ float g_sum [3 * NINS * 64];
__device__ float g_sum2[3 * NINS * 64];
__device__ float g_mean[3 * NINS * 64];
__device__ float g_rinv[3 * NINS * 64];
__device__ int   g_cnt [NINS];
__device__ int   g_ymin[NINS], g_ymax[NINS], g_xmin[NINS], g_xmax[NINS];
__device__ int   g_dil[3 * NINS];
// prepped weights (float2 units for aligned vector loads):
// [br][tap][(s*64+col)*4+tig] -> float2, col = cout, k = s*8+tig+4h
__device__ float2 g_wtb [3 * 9 * 2048];
__device__ float2 g_wtf2[36 * 2048];

// ---------------- helpers ----------------
__device__ __forceinline__ float tf32r(float x) {
    uint32_t u;
    asm("cvt.rna.tf32.f32 %0, %1;" : "=r"(u) : "f"(x));
    return __uint_as_float(u);
}

__device__ __forceinline__ void mma_tf32(float* d, const float* a, const float* b) {
    uint32_t a0 = __float_as_uint(a[0]), a1 = __float_as_uint(a[1]);
    uint32_t a2 = __float_as_uint(a[2]), a3 = __float_as_uint(a[3]);
    uint32_t b0 = __float_as_uint(b[0]), b1 = __float_as_uint(b[1]);
    asm volatile(
        "mma.sync.aligned.m16n8k8.row.col.f32.tf32.tf32.f32 "
        "{%0,%1,%2,%3}, {%4,%5,%6,%7}, {%8,%9}, {%0,%1,%2,%3};"
        : "+f"(d[0]), "+f"(d[1]), "+f"(d[2]), "+f"(d[3])
        : "r"(a0), "r"(a1), "r"(a2), "r"(a3), "r"(b0), "r"(b1));
}

#define APAD 68
#define SA_ELEMS (128 * APAD)

// ---------------- init / scatter / dil (proven) ----------------
__global__ void k_init() {
    int i = blockIdx.x * blockDim.x + threadIdx.x;
    if (i < Bn * Hn * Wn) g_idx_map[i] = -1;
    if (i < 3 * NINS * 64) { g_sum[i] = 0.f; g_sum2[i] = 0.f; }
    if (i < NINS) {
        g_cnt[i] = 0;
        g_ymin[i] = 0x7FFFFFFF; g_ymax[i] = 0x80000000;
        g_xmin[i] = 0x7FFFFFFF; g_xmax[i] = 0x80000000;
    }
}

__global__ void k_scatter(const int* __restrict__ idxs, const int* __restrict__ seg) {
    __shared__ int sy0[NINS], sy1[NINS], sx0[NINS], sx1[NINS], sc[NINS];
    int tid = threadIdx.x;
    if (tid < NINS) { sy0[tid] = 0x7FFFFFFF; sy1[tid] = 0x80000000;
                      sx0[tid] = 0x7FFFFFFF; sx1[tid] = 0x80000000; sc[tid] = 0; }
    __syncthreads();
    int i = blockIdx.x * blockDim.x + tid;
    if (i < Np) {
        int b = idxs[3*i], y = idxs[3*i+1], x = idxs[3*i+2];
        g_idx_map[(b * Hn + y) * Wn + x] = i;
        int s = seg[i];
        atomicMin(&sy0[s], y); atomicMax(&sy1[s], y);
        atomicMin(&sx0[s], x); atomicMax(&sx1[s], x);
        atomicAdd(&sc[s], 1);
    }
    __syncthreads();
    if (tid < NINS && sc[tid] > 0) {
        atomicMin(&g_ymin[tid], sy0[tid]); atomicMax(&g_ymax[tid], sy1[tid]);
        atomicMin(&g_xmin[tid], sx0[tid]); atomicMax(&g_xmax[tid], sx1[tid]);
        atomicAdd(&g_cnt[tid], sc[tid]);
    }
}

__global__ void k_dil() {
    int i = threadIdx.x;
    if (i < 3 * NINS) {
        int s = i & 15, r = i >> 4;
        int rate = (r == 0) ? 1 : (r == 1) ? 3 : 5;
        float hr = (float)(g_ymax[s] - g_ymin[s]) / (float)Hn;
        float wr = (float)(g_xmax[s] - g_xmin[s]) / (float)Wn;
        int d = (int)ceilf(fmaxf(hr, wr) * (float)rate);
        if (d < 1) d = 1;
        g_dil[r * NINS + s] = d;
    }
}

// ---------------- weight prep (proven layout) ----------------
__global__ void k_prepw(const float* __restrict__ w1, const float* __restrict__ w2,
                        const float* __restrict__ w3, const float* __restrict__ wf)
{
    int i = blockIdx.x * blockDim.x + threadIdx.x;
    if (i < 110592) {
        int br  = i / 36864;
        int r   = i % 36864;
        int tap = r / 4096;
        int r2  = r % 4096;
        int s   = r2 >> 9;
        int col = (r2 >> 3) & 63;
        int j   = r2 & 7;
        int k   = s * 8 + (j >> 1) + 4 * (j & 1);
        const float* w = (br == 0) ? w1 : (br == 1) ? w2 : w3;
        ((float*)g_wtb)[i] = tf32r(w[tap * 4096 + k * 64 + col]);
    } else if (i < 110592 + 147456) {
        int i2  = i - 110592;
        int u   = i2 / 4096;
        int r2  = i2 % 4096;
        int s   = r2 >> 9;
        int col = (r2 >> 3) & 63;
        int j   = r2 & 7;
        int tap = u >> 2, c = u & 3;
        int k   = c * 64 + s * 8 + (j >> 1) + 4 * (j & 1);
        ((float*)g_wtf2)[i2] = tf32r(wf[((size_t)tap * 256 + k) * 64 + col]);
    }
}

// ---------------- branch conv: 8 warps 32x32 tiles, B direct from L1 -------
__global__ void __launch_bounds__(256) k_branch_mma(
    const float* __restrict__ feats, const int* __restrict__ idxs,
    const int* __restrict__ seg,
    const float* __restrict__ bias1, const float* __restrict__ bias2,
    const float* __restrict__ bias3)
{
    extern __shared__ float sm[];
    float* sA   = sm;                               // [128][68]
    int*   snbr = (int*)(sm + SA_ELEMS);            // 128*9

    int tid = threadIdx.x;
    int br  = blockIdx.y;
    int p0  = blockIdx.x * 128;
    const float* bias = (br == 0) ? bias1 : (br == 1) ? bias2 : bias3;

    for (int t = tid; t < 128 * 9; t += 256) {
        int p = t / 9, k = t % 9;
        int gi = p0 + p;
        int b = idxs[3*gi], y = idxs[3*gi+1], x = idxs[3*gi+2];
        int sgi = seg[gi];
        int d = g_dil[br * NINS + sgi];
        int ky = k / 3 - 1, kx = k % 3 - 1;
        int ny = y + ky * d, nx = x + kx * d;
        int nbr = -1;
        if (ny >= 0 && ny < Hn && nx >= 0 && nx < Wn) {
            int n = g_idx_map[(b * Hn + ny) * Wn + nx];
            if (n >= 0 && seg[n] == sgi) nbr = n;
        }
        snbr[t] = nbr;
    }
    __syncthreads();

    int lane = tid & 31, wid = tid >> 5;
    int wm = wid >> 1, wn = wid & 1;
    int gid = lane >> 2, tig = lane & 3;
    int sub = lane >> 4, li = lane & 15;

    float acc[2][4][4];
#pragma unroll
    for (int mi = 0; mi < 2; mi++)
#pragma unroll
        for (int ni = 0; ni < 4; ni++)
#pragma unroll
            for (int e = 0; e < 4; e++) acc[mi][ni][e] = 0.f;

    const float2* wtb = g_wtb + (size_t)(br * 9) * 2048;

    for (int k = 0; k < 9; k++) {
        // A fill: coalesced gather, 2 rows per warp-instr
#pragma unroll
        for (int j = 0; j < 8; j++) {
            int row = wid * 16 + j * 2 + sub;
            int nbr = snbr[row * 9 + k];
            float4 f = make_float4(0.f, 0.f, 0.f, 0.f);
            if (nbr >= 0) f = ((const float4*)(feats + (size_t)nbr * 64))[li];
            f.x = tf32r(f.x); f.y = tf32r(f.y);
            f.z = tf32r(f.z); f.w = tf32r(f.w);
            *(float4*)(sA + row * APAD + li * 4) = f;
        }
        __syncthreads();

        const float2* wk = wtb + k * 2048;
#pragma unroll
        for (int s = 0; s < 8; s++) {
            float a[2][4];
#pragma unroll
            for (int mi = 0; mi < 2; mi++) {
                const float* ap = sA + (wm * 32 + mi * 16 + gid) * APAD + s * 8 + tig;
                a[mi][0] = ap[0];
                a[mi][1] = ap[8 * APAD];
                a[mi][2] = ap[4];
                a[mi][3] = ap[8 * APAD + 4];
            }
#pragma unroll
            for (int ni = 0; ni < 4; ni++) {
                float2 bb = __ldg(wk + (s * 64 + wn * 32 + ni * 8 + gid) * 4 + tig);
                mma_tf32(acc[0][ni], a[0], (const float*)&bb);
                mma_tf32(acc[1][ni], a[1], (const float*)&bb);
            }
        }
        __syncthreads();
    }

    float* hout = g_h + (size_t)br * Np * 64;
#pragma unroll
    for (int ni = 0; ni < 4; ni++) {
        int col = wn * 32 + ni * 8 + tig * 2;
        float2 bb = *(const float2*)(bias + col);
#pragma unroll
        for (int mi = 0; mi < 2; mi++) {
            int row = p0 + wm * 32 + mi * 16 + gid;
            float2 v0 = make_float2(acc[mi][ni][0] + bb.x, acc[mi][ni][1] + bb.y);
            float2 v1 = make_float2(acc[mi][ni][2] + bb.x, acc[mi][ni][3] + bb.y);
            *(float2*)(hout + (size_t)row * 64 + col) = v0;
            *(float2*)(hout + (size_t)(row + 8) * 64 + col) = v1;
        }
    }
}

// ---------------- segment stats (proven) ----------------
__global__ void k_stats(const int* __restrict__ seg) {
    int br   = blockIdx.y;
    int base = blockIdx.x * 1024;
    int c  = threadIdx.x & 63;
    int rs = threadIdx.x >> 6;
    const float* h = g_h + (size_t)br * Np * 64;
    float s = 0.f, s2 = 0.f;
    int cur = seg[base + rs];
    for (int j = 0; j < 256; j++) {
        int p = base + rs + 4 * j;
        int sg = seg[p];
        if (sg != cur) {
            atomicAdd(&g_sum [(br * NINS + cur) * 64 + c], s);
            atomicAdd(&g_sum2[(br * NINS + cur) * 64 + c], s2);
            s = 0.f; s2 = 0.f; cur = sg;
        }
        float v = h[(size_t)p * 64 + c];
        s += v; s2 += v * v;
    }
    atomicAdd(&g_sum [(br * NINS + cur) * 64 + c], s);
    atomicAdd(&g_sum2[(br * NINS + cur) * 64 + c], s2);
}

__global__ void k_normfin() {
    int i = blockIdx.x * blockDim.x + threadIdx.x;
    if (i < 3 * NINS * 64) {
        int sgl = (i / 64) % NINS;
        float cnt = (float)g_cnt[sgl];
        float mean = g_sum[i] / cnt;
        float var  = g_sum2[i] / cnt - mean * mean;
        g_mean[i] = mean;
        g_rinv[i] = rsqrtf(var + EPSF);
    }
}

// ---------------- normalize + relu + fp16 pack ----------------
// one thread per float4 unit: 3*Np*16 units; unit i -> g_hn[i] (uint2)
__global__ void __launch_bounds__(256) k_hnorm(const int* __restrict__ seg) {
    int i = blockIdx.x * 256 + threadIdx.x;
    int br  = i / (Np * 16);
    int rem = i % (Np * 16);
    int p   = rem >> 4;
    int c4  = rem & 15;
    int sg  = seg[p];
    float4 hv = ((const float4*)g_h)[i];
    int tb = ((br * NINS + sg) << 6) + c4 * 4;
    float4 mm = *(const float4*)(g_mean + tb);
    float4 rr = *(const float4*)(g_rinv + tb);
    float x0 = fmaxf(0.f, (hv.x - mm.x) * rr.x);
    float x1 = fmaxf(0.f, (hv.y - mm.y) * rr.y);
    float x2 = fmaxf(0.f, (hv.z - mm.z) * rr.z);
    float x3 = fmaxf(0.f, (hv.w - mm.w) * rr.w);
    __half2 h01 = __floats2half2_rn(x0, x1);
    __half2 h23 = __floats2half2_rn(x2, x3);
    uint32_t u01 = *(uint32_t*)&h01;
    uint32_t u23 = *(uint32_t*)&h23;
    g_hn[i] = make_uint2(u01, u23);
}

// ---------------- final conv: 8 warps 32x32 tiles, fp16 h gather -----------
__global__ void __launch_bounds__(256) k_final_mma(
    const float* __restrict__ feats, const int* __restrict__ idxs,
    const float* __restrict__ bf, float* __restrict__ out)
{
    extern __shared__ float sm[];
    float* sA    = sm;
    int*   snbr  = (int*)(sm + SA_ELEMS);

    int tid = threadIdx.x;
    int p0  = blockIdx.x * 128;

    for (int t = tid; t < 128 * 9; t += 256) {
        int p = t / 9, k = t % 9;
        int gi = p0 + p;
        int b = idxs[3*gi], y = idxs[3*gi+1], x = idxs[3*gi+2];
        int ky = k / 3 - 1, kx = k % 3 - 1;
        int ny = y + ky, nx = x + kx;
        int nbr = -1;
        if (ny >= 0 && ny < Hn && nx >= 0 && nx < Wn)
            nbr = g_idx_map[(b * Hn + ny) * Wn + nx];
        snbr[t] = nbr;
    }
    __syncthreads();

    int lane = tid & 31, wid = tid >> 5;
    int wm = wid >> 1, wn = wid & 1;
    int gid = lane >> 2, tig = lane & 3;
    int sub = lane >> 4, li = lane & 15;

    float acc[2][4][4];
#pragma unroll
    for (int mi = 0; mi < 2; mi++)
#pragma unroll
        for (int ni = 0; ni < 4; ni++)
#pragma unroll
            for (int e = 0; e < 4; e++) acc[mi][ni][e] = 0.f;

    for (int u = 0; u < 36; u++) {
        int k = u >> 2, c = u & 3;

        // A fill
        if (c == 0) {
#pragma unroll
            for (int j = 0; j < 8; j++) {
                int row = wid * 16 + j * 2 + sub;
                int nbr = snbr[row * 9 + k];
                float4 f = make_float4(0.f, 0.f, 0.f, 0.f);
                if (nbr >= 0) f = ((const float4*)(feats + (size_t)nbr * 64))[li];
                f.x = tf32r(f.x); f.y = tf32r(f.y);
                f.z = tf32r(f.z); f.w = tf32r(f.w);
                *(float4*)(sA + row * APAD + li * 4) = f;
            }
        } else {
            int brr = c - 1;
            const uint2* hnb = g_hn + (size_t)brr * Np * 16;
#pragma unroll
            for (int j = 0; j < 8; j++) {
                int row = wid * 16 + j * 2 + sub;
                int nbr = snbr[row * 9 + k];
                float4 v = make_float4(0.f, 0.f, 0.f, 0.f);
                if (nbr >= 0) {
                    uint2 raw = __ldg(hnb + (size_t)nbr * 16 + li);
                    float2 f01 = __half22float2(*reinterpret_cast<const __half2*>(&raw.x));
                    float2 f23 = __half22float2(*reinterpret_cast<const __half2*>(&raw.y));
                    v = make_float4(f01.x, f01.y, f23.x, f23.y);  // fp16->fp32 exact, tf32-valid
                }
                *(float4*)(sA + row * APAD + li * 4) = v;
            }
        }
        __syncthreads();

        const float2* wk = g_wtf2 + u * 2048;
#pragma unroll
        for (int s = 0; s < 8; s++) {
            float a[2][4];
#pragma unroll
            for (int mi = 0; mi < 2; mi++) {
                const float* ap = sA + (wm * 32 + mi * 16 + gid) * APAD + s * 8 + tig;
                a[mi][0] = ap[0];
                a[mi][1] = ap[8 * APAD];
                a[mi][2] = ap[4];
                a[mi][3] = ap[8 * APAD + 4];
            }
#pragma unroll
            for (int ni = 0; ni < 4; ni++) {
                float2 bb = __ldg(wk + (s * 64 + wn * 32 + ni * 8 + gid) * 4 + tig);
                mma_tf32(acc[0][ni], a[0], (const float*)&bb);
                mma_tf32(acc[1][ni], a[1], (const float*)&bb);
            }
        }
        __syncthreads();
    }

#pragma unroll
    for (int ni = 0; ni < 4; ni++) {
        int col = wn * 32 + ni * 8 + tig * 2;
        float2 bb = *(const float2*)(bf + col);
#pragma unroll
        for (int mi = 0; mi < 2; mi++) {
            int row = p0 + wm * 32 + mi * 16 + gid;
            float2 v0 = make_float2(acc[mi][ni][0] + bb.x, acc[mi][ni][1] + bb.y);
            float2 v1 = make_float2(acc[mi][ni][2] + bb.x, acc[mi][ni][3] + bb.y);
            *(float2*)(out + (size_t)row * 64 + col) = v0;
            *(float2*)(out + (size_t)(row + 8) * 64 + col) = v1;
        }
    }
}

// ---------------- launch ----------------
#define SMEM_CONV ((SA_ELEMS + 128 * 9) * 4)

extern "C" void kernel_launch(void* const* d_in, const int* in_sizes, int n_in,
                              void* d_out, int out_size)
{
    const float* feats = (const float*)d_in[0];
    const int*   idxs  = (const int*)  d_in[1];
    const int*   seg   = (const int*)  d_in[2];
    const float* w1    = (const float*)d_in[3];
    const float* b1    = (const float*)d_in[4];
    const float* w2    = (const float*)d_in[5];
    const float* b2    = (const float*)d_in[6];
    const float* w3    = (const float*)d_in[7];
    const float* b3    = (const float*)d_in[8];
    const float* wf    = (const float*)d_in[9];
    const float* bf    = (const float*)d_in[10];
    float* out = (float*)d_out;

    cudaFuncSetAttribute(k_branch_mma, cudaFuncAttributeMaxDynamicSharedMemorySize, SMEM_CONV);
    cudaFuncSetAttribute(k_final_mma,  cudaFuncAttributeMaxDynamicSharedMemorySize, SMEM_CONV);

    k_init<<<(Bn * Hn * Wn + 255) / 256, 256>>>();
    k_scatter<<<(Np + 255) / 256, 256>>>(idxs, seg);
    k_dil<<<1, 64>>>();
    k_prepw<<<(110592 + 147456 + 255) / 256, 256>>>(w1, w2, w3, wf);

    dim3 gb(Np / 128, 3);
    k_branch_mma<<<gb, 256, SMEM_CONV>>>(feats, idxs, seg, b1, b2, b3);

    dim3 sg(Np / 1024, 3);
    k_stats<<<sg, 256>>>(seg);
    k_normfin<<<12, 256>>>();
    k_hnorm<<<3 * Np * 16 / 256, 256>>>(seg);

    k_final_mma<<<Np / 128, 256, SMEM_CONV>>>(feats, idxs, bf, out);
}

// round 9
// speedup vs baseline: 1.7188x; 1.3069x over previous
#include <cuda_runtime.h>
#include <cuda_fp16.h>
#include <cstdint>

#define Np   262144
#define Bn   4
#define Hn   512
#define Wn   512
#define NINS 16
#define EPSF 1e-5f

// ---------------- device scratch ----------------
__device__ int   g_idx_map[Bn * Hn * Wn];
__device__ float g_h[3u * Np * 64u];              // raw branch outputs fp32
__device__ uint2 g_hn[3u * Np * 16u];             // relu(norm(h)) fp16: 16 uint2/row
__device__ float g_sum [3 * NINS * 64];
__device__ float g_sum2[3 * NINS * 64];
__device__ float g_mean[3 * NINS * 64];
__device__ float g_rinv[3 * NINS * 64];
__device__ int   g_cnt [NINS];
__device__ int   g_ymin[NINS], g_ymax[NINS], g_xmin[NINS], g_xmax[NINS];
__device__ int   g_dil[3 * NINS];
// fp16 fragment-packed weights:
// branch: [br][tap][(s*64+col)*4+tig] -> uint2 { half2(w[k0],w[k1]), half2(w[k8],w[k9]) }
//   k0 = s*16 + tig*2, k1 = k0+1, k8 = k0+8, k9 = k0+9   (s = 0..3, K=64)
__device__ uint2 g_wtbH[3 * 9 * 1024];
// final: [u=tap*4+c][(s*64+col)*4+tig], k = c*64 + s*16 + tig*2 (+1, +8, +9)
__device__ uint2 g_wtfH[36 * 1024];

// ---------------- helpers ----------------
__device__ __forceinline__ void mma_f16(float* d, uint32_t a0, uint32_t a1,
                                        uint32_t a2, uint32_t a3,
                                        uint32_t b0, uint32_t b1) {
    asm volatile(
        "mma.sync.aligned.m16n8k16.row.col.f32.f16.f16.f32 "
        "{%0,%1,%2,%3}, {%4,%5,%6,%7}, {%8,%9}, {%0,%1,%2,%3};"
        : "+f"(d[0]), "+f"(d[1]), "+f"(d[2]), "+f"(d[3])
        : "r"(a0), "r"(a1), "r"(a2), "r"(a3), "r"(b0), "r"(b1));
}

__device__ __forceinline__ uint32_t pack2(float x, float y) {
    __half2 h = __floats2half2_rn(x, y);
    return *(uint32_t*)&h;
}

#define APADH 72                      // halves per A row (64 + 8 pad), 144 B
#define SA_HALVES (128 * APADH)

// ---------------- init / scatter / dil (proven) ----------------
__global__ void k_init() {
    int i = blockIdx.x * blockDim.x + threadIdx.x;
    if (i < Bn * Hn * Wn) g_idx_map[i] = -1;
    if (i < 3 * NINS * 64) { g_sum[i] = 0.f; g_sum2[i] = 0.f; }
    if (i < NINS) {
        g_cnt[i] = 0;
        g_ymin[i] = 0x7FFFFFFF; g_ymax[i] = 0x80000000;
        g_xmin[i] = 0x7FFFFFFF; g_xmax[i] = 0x80000000;
    }
}

__global__ void k_scatter(const int* __restrict__ idxs, const int* __restrict__ seg) {
    __shared__ int sy0[NINS], sy1[NINS], sx0[NINS], sx1[NINS], sc[NINS];
    int tid = threadIdx.x;
    if (tid < NINS) { sy0[tid] = 0x7FFFFFFF; sy1[tid] = 0x80000000;
                      sx0[tid] = 0x7FFFFFFF; sx1[tid] = 0x80000000; sc[tid] = 0; }
    __syncthreads();
    int i = blockIdx.x * blockDim.x + tid;
    if (i < Np) {
        int b = idxs[3*i], y = idxs[3*i+1], x = idxs[3*i+2];
        g_idx_map[(b * Hn + y) * Wn + x] = i;
        int s = seg[i];
        atomicMin(&sy0[s], y); atomicMax(&sy1[s], y);
        atomicMin(&sx0[s], x); atomicMax(&sx1[s], x);
        atomicAdd(&sc[s], 1);
    }
    __syncthreads();
    if (tid < NINS && sc[tid] > 0) {
        atomicMin(&g_ymin[tid], sy0[tid]); atomicMax(&g_ymax[tid], sy1[tid]);
        atomicMin(&g_xmin[tid], sx0[tid]); atomicMax(&g_xmax[tid], sx1[tid]);
        atomicAdd(&g_cnt[tid], sc[tid]);
    }
}

__global__ void k_dil() {
    int i = threadIdx.x;
    if (i < 3 * NINS) {
        int s = i & 15, r = i >> 4;
        int rate = (r == 0) ? 1 : (r == 1) ? 3 : 5;
        float hr = (float)(g_ymax[s] - g_ymin[s]) / (float)Hn;
        float wr = (float)(g_xmax[s] - g_xmin[s]) / (float)Wn;
        int d = (int)ceilf(fmaxf(hr, wr) * (float)rate);
        if (d < 1) d = 1;
        g_dil[r * NINS + s] = d;
    }
}

// ---------------- weight prep: fp16 fragment pack ----------------
__global__ void k_prepw(const float* __restrict__ w1, const float* __restrict__ w2,
                        const float* __restrict__ w3, const float* __restrict__ wf)
{
    int i = blockIdx.x * blockDim.x + threadIdx.x;
    if (i < 27648) {                                  // 3 * 9 * 1024
        int br  = i / 9216;
        int r   = i % 9216;
        int tap = r / 1024;
        int r2  = r % 1024;
        int s   = r2 >> 8;
        int col = (r2 >> 2) & 63;
        int tig = r2 & 3;
        int kb  = s * 16 + tig * 2;
        const float* w = (br == 0) ? w1 : (br == 1) ? w2 : w3;
        const float* wt = w + tap * 4096;
        g_wtbH[i] = make_uint2(
            pack2(wt[(kb    ) * 64 + col], wt[(kb + 1) * 64 + col]),
            pack2(wt[(kb + 8) * 64 + col], wt[(kb + 9) * 64 + col]));
    } else if (i < 27648 + 36864) {                   // 36 * 1024
        int i2  = i - 27648;
        int u   = i2 / 1024;
        int r2  = i2 % 1024;
        int s   = r2 >> 8;
        int col = (r2 >> 2) & 63;
        int tig = r2 & 3;
        int tap = u >> 2, c = u & 3;
        int kb  = c * 64 + s * 16 + tig * 2;
        const float* wt = wf + (size_t)tap * 256 * 64;
        g_wtfH[i2] = make_uint2(
            pack2(wt[(kb    ) * 64 + col], wt[(kb + 1) * 64 + col]),
            pack2(wt[(kb + 8) * 64 + col], wt[(kb + 9) * 64 + col]));
    }
}

// ---------------- branch conv: fp16 mma, 8 warps 32x32 tiles ---------------
__global__ void __launch_bounds__(256) k_branch_mma(
    const float* __restrict__ feats, const int* __restrict__ idxs,
    const int* __restrict__ seg,
    const float* __restrict__ bias1, const float* __restrict__ bias2,
    const float* __restrict__ bias3)
{
    extern __shared__ __half smh[];
    __half* sA   = smh;                             // [128][72] halves
    int*    snbr = (int*)(smh + SA_HALVES);         // 128*9

    int tid = threadIdx.x;
    int br  = blockIdx.y;
    int p0  = blockIdx.x * 128;
    const float* bias = (br == 0) ? bias1 : (br == 1) ? bias2 : bias3;

    for (int t = tid; t < 128 * 9; t += 256) {
        int p = t / 9, k = t % 9;
        int gi = p0 + p;
        int b = idxs[3*gi], y = idxs[3*gi+1], x = idxs[3*gi+2];
        int sgi = seg[gi];
        int d = g_dil[br * NINS + sgi];
        int ky = k / 3 - 1, kx = k % 3 - 1;
        int ny = y + ky * d, nx = x + kx * d;
        int nbr = -1;
        if (ny >= 0 && ny < Hn && nx >= 0 && nx < Wn) {
            int n = g_idx_map[(b * Hn + ny) * Wn + nx];
            if (n >= 0 && seg[n] == sgi) nbr = n;
        }
        snbr[t] = nbr;
    }
    __syncthreads();

    int lane = tid & 31, wid = tid >> 5;
    int wm = wid >> 1, wn = wid & 1;
    int gid = lane >> 2, tig = lane & 3;
    int sub = lane >> 4, li = lane & 15;

    float acc[2][4][4];
#pragma unroll
    for (int mi = 0; mi < 2; mi++)
#pragma unroll
        for (int ni = 0; ni < 4; ni++)
#pragma unroll
            for (int e = 0; e < 4; e++) acc[mi][ni][e] = 0.f;

    const uint2* wtb = g_wtbH + (size_t)(br * 9) * 1024;

    for (int k = 0; k < 9; k++) {
        // A fill: gather fp32 feats, convert to fp16 (2 rows/warp-instr)
#pragma unroll
        for (int j = 0; j < 8; j++) {
            int row = wid * 16 + j * 2 + sub;
            int nbr = snbr[row * 9 + k];
            uint2 v = make_uint2(0u, 0u);
            if (nbr >= 0) {
                float4 f = ((const float4*)(feats + (size_t)nbr * 64))[li];
                v = make_uint2(pack2(f.x, f.y), pack2(f.z, f.w));
            }
            *(uint2*)((char*)sA + row * 144 + li * 8) = v;
        }
        __syncthreads();

        const uint2* wk = wtb + k * 1024;
#pragma unroll
        for (int s = 0; s < 4; s++) {
            uint32_t a[2][4];
#pragma unroll
            for (int mi = 0; mi < 2; mi++) {
                const __half* ap = sA + (wm * 32 + mi * 16 + gid) * APADH + s * 16 + tig * 2;
                a[mi][0] = *(const uint32_t*)(ap);
                a[mi][1] = *(const uint32_t*)(ap + 8 * APADH);
                a[mi][2] = *(const uint32_t*)(ap + 8);
                a[mi][3] = *(const uint32_t*)(ap + 8 * APADH + 8);
            }
#pragma unroll
            for (int ni = 0; ni < 4; ni++) {
                uint2 bb = __ldg(wk + (s * 64 + wn * 32 + ni * 8 + gid) * 4 + tig);
                mma_f16(acc[0][ni], a[0][0], a[0][1], a[0][2], a[0][3], bb.x, bb.y);
                mma_f16(acc[1][ni], a[1][0], a[1][1], a[1][2], a[1][3], bb.x, bb.y);
            }
        }
        __syncthreads();
    }

    float* hout = g_h + (size_t)br * Np * 64;
#pragma unroll
    for (int ni = 0; ni < 4; ni++) {
        int col = wn * 32 + ni * 8 + tig * 2;
        float2 bb = *(const float2*)(bias + col);
#pragma unroll
        for (int mi = 0; mi < 2; mi++) {
            int row = p0 + wm * 32 + mi * 16 + gid;
            float2 v0 = make_float2(acc[mi][ni][0] + bb.x, acc[mi][ni][1] + bb.y);
            float2 v1 = make_float2(acc[mi][ni][2] + bb.x, acc[mi][ni][3] + bb.y);
            *(float2*)(hout + (size_t)row * 64 + col) = v0;
            *(float2*)(hout + (size_t)(row + 8) * 64 + col) = v1;
        }
    }
}

// ---------------- segment stats (proven) ----------------
__global__ void k_stats(const int* __restrict__ seg) {
    int br   = blockIdx.y;
    int base = blockIdx.x * 1024;
    int c  = threadIdx.x & 63;
    int rs = threadIdx.x >> 6;
    const float* h = g_h + (size_t)br * Np * 64;
    float s = 0.f, s2 = 0.f;
    int cur = seg[base + rs];
    for (int j = 0; j < 256; j++) {
        int p = base + rs + 4 * j;
        int sg = seg[p];
        if (sg != cur) {
            atomicAdd(&g_sum [(br * NINS + cur) * 64 + c], s);
            atomicAdd(&g_sum2[(br * NINS + cur) * 64 + c], s2);
            s = 0.f; s2 = 0.f; cur = sg;
        }
        float v = h[(size_t)p * 64 + c];
        s += v; s2 += v * v;
    }
    atomicAdd(&g_sum [(br * NINS + cur) * 64 + c], s);
    atomicAdd(&g_sum2[(br * NINS + cur) * 64 + c], s2);
}

__global__ void k_normfin() {
    int i = blockIdx.x * blockDim.x + threadIdx.x;
    if (i < 3 * NINS * 64) {
        int sgl = (i / 64) % NINS;
        float cnt = (float)g_cnt[sgl];
        float mean = g_sum[i] / cnt;
        float var  = g_sum2[i] / cnt - mean * mean;
        g_mean[i] = mean;
        g_rinv[i] = rsqrtf(var + EPSF);
    }
}

// ---------------- normalize + relu + fp16 pack ----------------
__global__ void __launch_bounds__(256) k_hnorm(const int* __restrict__ seg) {
    int i = blockIdx.x * 256 + threadIdx.x;
    int br  = i / (Np * 16);
    int rem = i % (Np * 16);
    int p   = rem >> 4;
    int c4  = rem & 15;
    int sg  = seg[p];
    float4 hv = ((const float4*)g_h)[i];
    int tb = ((br * NINS + sg) << 6) + c4 * 4;
    float4 mm = *(const float4*)(g_mean + tb);
    float4 rr = *(const float4*)(g_rinv + tb);
    float x0 = fmaxf(0.f, (hv.x - mm.x) * rr.x);
    float x1 = fmaxf(0.f, (hv.y - mm.y) * rr.y);
    float x2 = fmaxf(0.f, (hv.z - mm.z) * rr.z);
    float x3 = fmaxf(0.f, (hv.w - mm.w) * rr.w);
    g_hn[i] = make_uint2(pack2(x0, x1), pack2(x2, x3));
}

// ---------------- final conv: fp16 mma, g_hn direct copy -------------------
__global__ void __launch_bounds__(256) k_final_mma(
    const float* __restrict__ feats, const int* __restrict__ idxs,
    const float* __restrict__ bf, float* __restrict__ out)
{
    extern __shared__ __half smh[];
    __half* sA   = smh;
    int*    snbr = (int*)(smh + SA_HALVES);

    int tid = threadIdx.x;
    int p0  = blockIdx.x * 128;

    for (int t = tid; t < 128 * 9; t += 256) {
        int p = t / 9, k = t % 9;
        int gi = p0 + p;
        int b = idxs[3*gi], y = idxs[3*gi+1], x = idxs[3*gi+2];
        int ky = k / 3 - 1, kx = k % 3 - 1;
        int ny = y + ky, nx = x + kx;
        int nbr = -1;
        if (ny >= 0 && ny < Hn && nx >= 0 && nx < Wn)
            nbr = g_idx_map[(b * Hn + ny) * Wn + nx];
        snbr[t] = nbr;
    }
    __syncthreads();

    int lane = tid & 31, wid = tid >> 5;
    int wm = wid >> 1, wn = wid & 1;
    int gid = lane >> 2, tig = lane & 3;
    int sub = lane >> 4, li = lane & 15;

    float acc[2][4][4];
#pragma unroll
    for (int mi = 0; mi < 2; mi++)
#pragma unroll
        for (int ni = 0; ni < 4; ni++)
#pragma unroll
            for (int e = 0; e < 4; e++) acc[mi][ni][e] = 0.f;

    for (int u = 0; u < 36; u++) {
        int k = u >> 2, c = u & 3;

        // A fill
        if (c == 0) {
#pragma unroll
            for (int j = 0; j < 8; j++) {
                int row = wid * 16 + j * 2 + sub;
                int nbr = snbr[row * 9 + k];
                uint2 v = make_uint2(0u, 0u);
                if (nbr >= 0) {
                    float4 f = ((const float4*)(feats + (size_t)nbr * 64))[li];
                    v = make_uint2(pack2(f.x, f.y), pack2(f.z, f.w));
                }
                *(uint2*)((char*)sA + row * 144 + li * 8) = v;
            }
        } else {
            int brr = c - 1;
            const uint2* hnb = g_hn + (size_t)brr * Np * 16;
#pragma unroll
            for (int j = 0; j < 8; j++) {
                int row = wid * 16 + j * 2 + sub;
                int nbr = snbr[row * 9 + k];
                uint2 v = make_uint2(0u, 0u);
                if (nbr >= 0) v = __ldg(hnb + (size_t)nbr * 16 + li);
                *(uint2*)((char*)sA + row * 144 + li * 8) = v;
            }
        }
        __syncthreads();

        const uint2* wk = g_wtfH + u * 1024;
#pragma unroll
        for (int s = 0; s < 4; s++) {
            uint32_t a[2][4];
#pragma unroll
            for (int mi = 0; mi < 2; mi++) {
                const __half* ap = sA + (wm * 32 + mi * 16 + gid) * APADH + s * 16 + tig * 2;
                a[mi][0] = *(const uint32_t*)(ap);
                a[mi][1] = *(const uint32_t*)(ap + 8 * APADH);
                a[mi][2] = *(const uint32_t*)(ap + 8);
                a[mi][3] = *(const uint32_t*)(ap + 8 * APADH + 8);
            }
#pragma unroll
            for (int ni = 0; ni < 4; ni++) {
                uint2 bb = __ldg(wk + (s * 64 + wn * 32 + ni * 8 + gid) * 4 + tig);
                mma_f16(acc[0][ni], a[0][0], a[0][1], a[0][2], a[0][3], bb.x, bb.y);
                mma_f16(acc[1][ni], a[1][0], a[1][1], a[1][2], a[1][3], bb.x, bb.y);
            }
        }
        __syncthreads();
    }

#pragma unroll
    for (int ni = 0; ni < 4; ni++) {
        int col = wn * 32 + ni * 8 + tig * 2;
        float2 bb = *(const float2*)(bf + col);
#pragma unroll
        for (int mi = 0; mi < 2; mi++) {
            int row = p0 + wm * 32 + mi * 16 + gid;
            float2 v0 = make_float2(acc[mi][ni][0] + bb.x, acc[mi][ni][1] + bb.y);
            float2 v1 = make_float2(acc[mi][ni][2] + bb.x, acc[mi][ni][3] + bb.y);
            *(float2*)(out + (size_t)row * 64 + col) = v0;
            *(float2*)(out + (size_t)(row + 8) * 64 + col) = v1;
        }
    }
}

// ---------------- launch ----------------
#define SMEM_CONV (SA_HALVES * 2 + 128 * 9 * 4)

extern "C" void kernel_launch(void* const* d_in, const int* in_sizes, int n_in,
                              void* d_out, int out_size)
{
    const float* feats = (const float*)d_in[0];
    const int*   idxs  = (const int*)  d_in[1];
    const int*   seg   = (const int*)  d_in[2];
    const float* w1    = (const float*)d_in[3];
    const float* b1    = (const float*)d_in[4];
    const float* w2    = (const float*)d_in[5];
    const float* b2    = (const float*)d_in[6];
    const float* w3    = (const float*)d_in[7];
    const float* b3    = (const float*)d_in[8];
    const float* wf    = (const float*)d_in[9];
    const float* bf    = (const float*)d_in[10];
    float* out = (float*)d_out;

    cudaFuncSetAttribute(k_branch_mma, cudaFuncAttributeMaxDynamicSharedMemorySize, SMEM_CONV);
    cudaFuncSetAttribute(k_final_mma,  cudaFuncAttributeMaxDynamicSharedMemorySize, SMEM_CONV);

    k_init<<<(Bn * Hn * Wn + 255) / 256, 256>>>();
    k_scatter<<<(Np + 255) / 256, 256>>>(idxs, seg);
    k_dil<<<1, 64>>>();
    k_prepw<<<(27648 + 36864 + 255) / 256, 256>>>(w1, w2, w3, wf);

    dim3 gb(Np / 128, 3);
    k_branch_mma<<<gb, 256, SMEM_CONV>>>(feats, idxs, seg, b1, b2, b3);

    dim3 sg(Np / 1024, 3);
    k_stats<<<sg, 256>>>(seg);
    k_normfin<<<12, 256>>>();
    k_hnorm<<<3 * Np * 16 / 256, 256>>>(seg);

    k_final_mma<<<Np / 128, 256, SMEM_CONV>>>(feats, idxs, bf, out);
}

// round 10
// speedup vs baseline: 1.9147x; 1.1140x over previous
#include <cuda_runtime.h>
#include <cuda_fp16.h>
#include <cstdint>

#define Np   262144
#define Bn   4
#define Hn   512
#define Wn   512
#define NINS 16
#define EPSF 1e-5f

// ---------------- device scratch ----------------
__device__ int   g_idx_map[Bn * Hn * Wn];
__device__ float g_h[3u * Np * 64u];              // raw branch outputs fp32
__device__ uint2 g_hn[3u * Np * 16u];             // relu(norm(h)) fp16: 16 uint2/row
__device__ uint2 g_ftH[Np * 16u];                 // feats fp16: 16 uint2/row
__device__ float g_sum [3 * NINS * 64];
__device__ float g_sum2[3 * NINS * 64];
__device__ float g_mean[3 * NINS * 64];
__device__ float g_rinv[3 * NINS * 64];
__device__ int   g_cnt [NINS];
__device__ int   g_ymin[NINS], g_ymax[NINS], g_xmin[NINS], g_xmax[NINS];
__device__ int   g_dil[3 * NINS];
// fp16 fragment-packed weights (proven layout from round 9)
__device__ uint2 g_wtbH[3 * 9 * 1024];
__device__ uint2 g_wtfH[36 * 1024];

// ---------------- helpers ----------------
__device__ __forceinline__ void mma_f16(float* d, uint32_t a0, uint32_t a1,
                                        uint32_t a2, uint32_t a3,
                                        uint32_t b0, uint32_t b1) {
    asm volatile(
        "mma.sync.aligned.m16n8k16.row.col.f32.f16.f16.f32 "
        "{%0,%1,%2,%3}, {%4,%5,%6,%7}, {%8,%9}, {%0,%1,%2,%3};"
        : "+f"(d[0]), "+f"(d[1]), "+f"(d[2]), "+f"(d[3])
        : "r"(a0), "r"(a1), "r"(a2), "r"(a3), "r"(b0), "r"(b1));
}

__device__ __forceinline__ uint32_t pack2(float x, float y) {
    __half2 h = __floats2half2_rn(x, y);
    return *(uint32_t*)&h;
}

#define APADH 72
#define SA_HALVES (128 * APADH)

// ---------------- init / scatter / dil (proven) ----------------
__global__ void k_init() {
    int i = blockIdx.x * blockDim.x + threadIdx.x;
    if (i < Bn * Hn * Wn) g_idx_map[i] = -1;
    if (i < 3 * NINS * 64) { g_sum[i] = 0.f; g_sum2[i] = 0.f; }
    if (i < NINS) {
        g_cnt[i] = 0;
        g_ymin[i] = 0x7FFFFFFF; g_ymax[i] = 0x80000000;
        g_xmin[i] = 0x7FFFFFFF; g_xmax[i] = 0x80000000;
    }
}

__global__ void k_scatter(const int* __restrict__ idxs, const int* __restrict__ seg) {
    __shared__ int sy0[NINS], sy1[NINS], sx0[NINS], sx1[NINS], sc[NINS];
    int tid = threadIdx.x;
    if (tid < NINS) { sy0[tid] = 0x7FFFFFFF; sy1[tid] = 0x80000000;
                      sx0[tid] = 0x7FFFFFFF; sx1[tid] = 0x80000000; sc[tid] = 0; }
    __syncthreads();
    int i = blockIdx.x * blockDim.x + tid;
    if (i < Np) {
        int b = idxs[3*i], y = idxs[3*i+1], x = idxs[3*i+2];
        g_idx_map[(b * Hn + y) * Wn + x] = i;
        int s = seg[i];
        atomicMin(&sy0[s], y); atomicMax(&sy1[s], y);
        atomicMin(&sx0[s], x); atomicMax(&sx1[s], x);
        atomicAdd(&sc[s], 1);
    }
    __syncthreads();
    if (tid < NINS && sc[tid] > 0) {
        atomicMin(&g_ymin[tid], sy0[tid]); atomicMax(&g_ymax[tid], sy1[tid]);
        atomicMin(&g_xmin[tid], sx0[tid]); atomicMax(&g_xmax[tid], sx1[tid]);
        atomicAdd(&g_cnt[tid], sc[tid]);
    }
}

__global__ void k_dil() {
    int i = threadIdx.x;
    if (i < 3 * NINS) {
        int s = i & 15, r = i >> 4;
        int rate = (r == 0) ? 1 : (r == 1) ? 3 : 5;
        float hr = (float)(g_ymax[s] - g_ymin[s]) / (float)Hn;
        float wr = (float)(g_xmax[s] - g_xmin[s]) / (float)Wn;
        int d = (int)ceilf(fmaxf(hr, wr) * (float)rate);
        if (d < 1) d = 1;
        g_dil[r * NINS + s] = d;
    }
}

// ---------------- weight prep: fp16 fragment pack (proven) ----------------
__global__ void k_prepw(const float* __restrict__ w1, const float* __restrict__ w2,
                        const float* __restrict__ w3, const float* __restrict__ wf)
{
    int i = blockIdx.x * blockDim.x + threadIdx.x;
    if (i < 27648) {
        int br  = i / 9216;
        int r   = i % 9216;
        int tap = r / 1024;
        int r2  = r % 1024;
        int s   = r2 >> 8;
        int col = (r2 >> 2) & 63;
        int tig = r2 & 3;
        int kb  = s * 16 + tig * 2;
        const float* w = (br == 0) ? w1 : (br == 1) ? w2 : w3;
        const float* wt = w + tap * 4096;
        g_wtbH[i] = make_uint2(
            pack2(wt[(kb    ) * 64 + col], wt[(kb + 1) * 64 + col]),
            pack2(wt[(kb + 8) * 64 + col], wt[(kb + 9) * 64 + col]));
    } else if (i < 27648 + 36864) {
        int i2  = i - 27648;
        int u   = i2 / 1024;
        int r2  = i2 % 1024;
        int s   = r2 >> 8;
        int col = (r2 >> 2) & 63;
        int tig = r2 & 3;
        int tap = u >> 2, c = u & 3;
        int kb  = c * 64 + s * 16 + tig * 2;
        const float* wt = wf + (size_t)tap * 256 * 64;
        g_wtfH[i2] = make_uint2(
            pack2(wt[(kb    ) * 64 + col], wt[(kb + 1) * 64 + col]),
            pack2(wt[(kb + 8) * 64 + col], wt[(kb + 9) * 64 + col]));
    }
}

// ---------------- feats -> fp16 pre-convert ----------------
__global__ void __launch_bounds__(256) k_prepf(const float* __restrict__ feats) {
    int i = blockIdx.x * 256 + threadIdx.x;      // Np*16 float4 units
    float4 f = ((const float4*)feats)[i];
    g_ftH[i] = make_uint2(pack2(f.x, f.y), pack2(f.z, f.w));
}

// ---------------- branch conv + fused stats ----------------
__global__ void __launch_bounds__(256) k_branch_mma(
    const int* __restrict__ idxs, const int* __restrict__ seg,
    const float* __restrict__ bias1, const float* __restrict__ bias2,
    const float* __restrict__ bias3)
{
    extern __shared__ __half smh[];
    __half* sA   = smh;                             // [128][72] halves
    int*    snbr = (int*)(smh + SA_HALVES);         // 128*9

    int tid = threadIdx.x;
    int br  = blockIdx.y;
    int p0  = blockIdx.x * 128;
    const float* bias = (br == 0) ? bias1 : (br == 1) ? bias2 : bias3;

    for (int t = tid; t < 128 * 9; t += 256) {
        int p = t / 9, k = t % 9;
        int gi = p0 + p;
        int b = idxs[3*gi], y = idxs[3*gi+1], x = idxs[3*gi+2];
        int sgi = seg[gi];
        int d = g_dil[br * NINS + sgi];
        int ky = k / 3 - 1, kx = k % 3 - 1;
        int ny = y + ky * d, nx = x + kx * d;
        int nbr = -1;
        if (ny >= 0 && ny < Hn && nx >= 0 && nx < Wn) {
            int n = g_idx_map[(b * Hn + ny) * Wn + nx];
            if (n >= 0 && seg[n] == sgi) nbr = n;
        }
        snbr[t] = nbr;
    }
    __syncthreads();

    int lane = tid & 31, wid = tid >> 5;
    int wm = wid >> 1, wn = wid & 1;
    int gid = lane >> 2, tig = lane & 3;
    int sub = lane >> 4, li = lane & 15;

    float acc[2][4][4];
#pragma unroll
    for (int mi = 0; mi < 2; mi++)
#pragma unroll
        for (int ni = 0; ni < 4; ni++)
#pragma unroll
            for (int e = 0; e < 4; e++) acc[mi][ni][e] = 0.f;

    const uint2* wtb = g_wtbH + (size_t)(br * 9) * 1024;

    for (int k = 0; k < 9; k++) {
        // A fill: gather fp16 feats rows (2 rows/warp-instr)
#pragma unroll
        for (int j = 0; j < 8; j++) {
            int row = wid * 16 + j * 2 + sub;
            int nbr = snbr[row * 9 + k];
            uint2 v = make_uint2(0u, 0u);
            if (nbr >= 0) v = __ldg(g_ftH + (size_t)nbr * 16 + li);
            *(uint2*)((char*)sA + row * 144 + li * 8) = v;
        }
        __syncthreads();

        const uint2* wk = wtb + k * 1024;
#pragma unroll
        for (int s = 0; s < 4; s++) {
            uint32_t a[2][4];
#pragma unroll
            for (int mi = 0; mi < 2; mi++) {
                const __half* ap = sA + (wm * 32 + mi * 16 + gid) * APADH + s * 16 + tig * 2;
                a[mi][0] = *(const uint32_t*)(ap);
                a[mi][1] = *(const uint32_t*)(ap + 8 * APADH);
                a[mi][2] = *(const uint32_t*)(ap + 8);
                a[mi][3] = *(const uint32_t*)(ap + 8 * APADH + 8);
            }
#pragma unroll
            for (int ni = 0; ni < 4; ni++) {
                uint2 bb = __ldg(wk + (s * 64 + wn * 32 + ni * 8 + gid) * 4 + tig);
                mma_f16(acc[0][ni], a[0][0], a[0][1], a[0][2], a[0][3], bb.x, bb.y);
                mma_f16(acc[1][ni], a[1][0], a[1][1], a[1][2], a[1][3], bb.x, bb.y);
            }
        }
        __syncthreads();
    }

    // add bias into acc, write h
    float* hout = g_h + (size_t)br * Np * 64;
#pragma unroll
    for (int ni = 0; ni < 4; ni++) {
        int col = wn * 32 + ni * 8 + tig * 2;
        float2 bb = *(const float2*)(bias + col);
#pragma unroll
        for (int mi = 0; mi < 2; mi++) {
            acc[mi][ni][0] += bb.x; acc[mi][ni][1] += bb.y;
            acc[mi][ni][2] += bb.x; acc[mi][ni][3] += bb.y;
            int row = p0 + wm * 32 + mi * 16 + gid;
            *(float2*)(hout + (size_t)row * 64 + col) =
                make_float2(acc[mi][ni][0], acc[mi][ni][1]);
            *(float2*)(hout + (size_t)(row + 8) * 64 + col) =
                make_float2(acc[mi][ni][2], acc[mi][ni][3]);
        }
    }

    // ---- fused segment stats ----
    int sg0 = seg[p0], sg1 = seg[p0 + 127];
    if (sg0 == sg1) {
        // uniform block: warp shuffle-reduce over gid, then 1 atomic per col value
#pragma unroll
        for (int ni = 0; ni < 4; ni++) {
            float s0 = acc[0][ni][0] + acc[0][ni][2] + acc[1][ni][0] + acc[1][ni][2];
            float s1 = acc[0][ni][1] + acc[0][ni][3] + acc[1][ni][1] + acc[1][ni][3];
            float q0 = acc[0][ni][0]*acc[0][ni][0] + acc[0][ni][2]*acc[0][ni][2]
                     + acc[1][ni][0]*acc[1][ni][0] + acc[1][ni][2]*acc[1][ni][2];
            float q1 = acc[0][ni][1]*acc[0][ni][1] + acc[0][ni][3]*acc[0][ni][3]
                     + acc[1][ni][1]*acc[1][ni][1] + acc[1][ni][3]*acc[1][ni][3];
#pragma unroll
            for (int m = 4; m < 32; m <<= 1) {
                s0 += __shfl_xor_sync(0xFFFFFFFF, s0, m);
                s1 += __shfl_xor_sync(0xFFFFFFFF, s1, m);
                q0 += __shfl_xor_sync(0xFFFFFFFF, q0, m);
                q1 += __shfl_xor_sync(0xFFFFFFFF, q1, m);
            }
            if (gid == 0) {
                int col = wn * 32 + ni * 8 + tig * 2;
                int tb = (br * NINS + sg0) * 64 + col;
                atomicAdd(&g_sum [tb],     s0);
                atomicAdd(&g_sum [tb + 1], s1);
                atomicAdd(&g_sum2[tb],     q0);
                atomicAdd(&g_sum2[tb + 1], q1);
            }
        }
    } else {
        // boundary block (rare): per-value atomics
#pragma unroll
        for (int ni = 0; ni < 4; ni++) {
            int col = wn * 32 + ni * 8 + tig * 2;
#pragma unroll
            for (int mi = 0; mi < 2; mi++) {
                int rowa = p0 + wm * 32 + mi * 16 + gid;
                int rowb = rowa + 8;
                int sa = seg[rowa], sb = seg[rowb];
                int ta = (br * NINS + sa) * 64 + col;
                int tb2 = (br * NINS + sb) * 64 + col;
                atomicAdd(&g_sum [ta],     acc[mi][ni][0]);
                atomicAdd(&g_sum [ta + 1], acc[mi][ni][1]);
                atomicAdd(&g_sum2[ta],     acc[mi][ni][0]*acc[mi][ni][0]);
                atomicAdd(&g_sum2[ta + 1], acc[mi][ni][1]*acc[mi][ni][1]);
                atomicAdd(&g_sum [tb2],     acc[mi][ni][2]);
                atomicAdd(&g_sum [tb2 + 1], acc[mi][ni][3]);
                atomicAdd(&g_sum2[tb2],     acc[mi][ni][2]*acc[mi][ni][2]);
                atomicAdd(&g_sum2[tb2 + 1], acc[mi][ni][3]*acc[mi][ni][3]);
            }
        }
    }
}

__global__ void k_normfin() {
    int i = blockIdx.x * blockDim.x + threadIdx.x;
    if (i < 3 * NINS * 64) {
        int sgl = (i / 64) % NINS;
        float cnt = (float)g_cnt[sgl];
        float mean = g_sum[i] / cnt;
        float var  = g_sum2[i] / cnt - mean * mean;
        g_mean[i] = mean;
        g_rinv[i] = rsqrtf(var + EPSF);
    }
}

// ---------------- normalize + relu + fp16 pack ----------------
__global__ void __launch_bounds__(256) k_hnorm(const int* __restrict__ seg) {
    int i = blockIdx.x * 256 + threadIdx.x;
    int br  = i / (Np * 16);
    int rem = i % (Np * 16);
    int p   = rem >> 4;
    int c4  = rem & 15;
    int sg  = seg[p];
    float4 hv = ((const float4*)g_h)[i];
    int tb = ((br * NINS + sg) << 6) + c4 * 4;
    float4 mm = *(const float4*)(g_mean + tb);
    float4 rr = *(const float4*)(g_rinv + tb);
    float x0 = fmaxf(0.f, (hv.x - mm.x) * rr.x);
    float x1 = fmaxf(0.f, (hv.y - mm.y) * rr.y);
    float x2 = fmaxf(0.f, (hv.z - mm.z) * rr.z);
    float x3 = fmaxf(0.f, (hv.w - mm.w) * rr.w);
    g_hn[i] = make_uint2(pack2(x0, x1), pack2(x2, x3));
}

// ---------------- final conv: fp16 mma, fp16 gathers ------------------------
__global__ void __launch_bounds__(256) k_final_mma(
    const int* __restrict__ idxs, const float* __restrict__ bf,
    float* __restrict__ out)
{
    extern __shared__ __half smh[];
    __half* sA   = smh;
    int*    snbr = (int*)(smh + SA_HALVES);

    int tid = threadIdx.x;
    int p0  = blockIdx.x * 128;

    for (int t = tid; t < 128 * 9; t += 256) {
        int p = t / 9, k = t % 9;
        int gi = p0 + p;
        int b = idxs[3*gi], y = idxs[3*gi+1], x = idxs[3*gi+2];
        int ky = k / 3 - 1, kx = k % 3 - 1;
        int ny = y + ky, nx = x + kx;
        int nbr = -1;
        if (ny >= 0 && ny < Hn && nx >= 0 && nx < Wn)
            nbr = g_idx_map[(b * Hn + ny) * Wn + nx];
        snbr[t] = nbr;
    }
    __syncthreads();

    int lane = tid & 31, wid = tid >> 5;
    int wm = wid >> 1, wn = wid & 1;
    int gid = lane >> 2, tig = lane & 3;
    int sub = lane >> 4, li = lane & 15;

    float acc[2][4][4];
#pragma unroll
    for (int mi = 0; mi < 2; mi++)
#pragma unroll
        for (int ni = 0; ni < 4; ni++)
#pragma unroll
            for (int e = 0; e < 4; e++) acc[mi][ni][e] = 0.f;

    for (int u = 0; u < 36; u++) {
        int k = u >> 2, c = u & 3;
        const uint2* src = (c == 0) ? g_ftH : (g_hn + (size_t)(c - 1) * Np * 16);

        // A fill: raw fp16 row copy
#pragma unroll
        for (int j = 0; j < 8; j++) {
            int row = wid * 16 + j * 2 + sub;
            int nbr = snbr[row * 9 + k];
            uint2 v = make_uint2(0u, 0u);
            if (nbr >= 0) v = __ldg(src + (size_t)nbr * 16 + li);
            *(uint2*)((char*)sA + row * 144 + li * 8) = v;
        }
        __syncthreads();

        const uint2* wk = g_wtfH + u * 1024;
#pragma unroll
        for (int s = 0; s < 4; s++) {
            uint32_t a[2][4];
#pragma unroll
            for (int mi = 0; mi < 2; mi++) {
                const __half* ap = sA + (wm * 32 + mi * 16 + gid) * APADH + s * 16 + tig * 2;
                a[mi][0] = *(const uint32_t*)(ap);
                a[mi][1] = *(const uint32_t*)(ap + 8 * APADH);
                a[mi][2] = *(const uint32_t*)(ap + 8);
                a[mi][3] = *(const uint32_t*)(ap + 8 * APADH + 8);
            }
#pragma unroll
            for (int ni = 0; ni < 4; ni++) {
                uint2 bb = __ldg(wk + (s * 64 + wn * 32 + ni * 8 + gid) * 4 + tig);
                mma_f16(acc[0][ni], a[0][0], a[0][1], a[0][2], a[0][3], bb.x, bb.y);
                mma_f16(acc[1][ni], a[1][0], a[1][1], a[1][2], a[1][3], bb.x, bb.y);
            }
        }
        __syncthreads();
    }

#pragma unroll
    for (int ni = 0; ni < 4; ni++) {
        int col = wn * 32 + ni * 8 + tig * 2;
        float2 bb = *(const float2*)(bf + col);
#pragma unroll
        for (int mi = 0; mi < 2; mi++) {
            int row = p0 + wm * 32 + mi * 16 + gid;
            float2 v0 = make_float2(acc[mi][ni][0] + bb.x, acc[mi][ni][1] + bb.y);
            float2 v1 = make_float2(acc[mi][ni][2] + bb.x, acc[mi][ni][3] + bb.y);
            *(float2*)(out + (size_t)row * 64 + col) = v0;
            *(float2*)(out + (size_t)(row + 8) * 64 + col) = v1;
        }
    }
}

// ---------------- launch ----------------
#define SMEM_CONV (SA_HALVES * 2 + 128 * 9 * 4)

extern "C" void kernel_launch(void* const* d_in, const int* in_sizes, int n_in,
                              void* d_out, int out_size)
{
    const float* feats = (const float*)d_in[0];
    const int*   idxs  = (const int*)  d_in[1];
    const int*   seg   = (const int*)  d_in[2];
    const float* w1    = (const float*)d_in[3];
    const float* b1    = (const float*)d_in[4];
    const float* w2    = (const float*)d_in[5];
    const float* b2    = (const float*)d_in[6];
    const float* w3    = (const float*)d_in[7];
    const float* b3    = (const float*)d_in[8];
    const float* wf    = (const float*)d_in[9];
    const float* bf    = (const float*)d_in[10];
    float* out = (float*)d_out;

    cudaFuncSetAttribute(k_branch_mma, cudaFuncAttributeMaxDynamicSharedMemorySize, SMEM_CONV);
    cudaFuncSetAttribute(k_final_mma,  cudaFuncAttributeMaxDynamicSharedMemorySize, SMEM_CONV);

    k_init<<<(Bn * Hn * Wn + 255) / 256, 256>>>();
    k_scatter<<<(Np + 255) / 256, 256>>>(idxs, seg);
    k_dil<<<1, 64>>>();
    k_prepw<<<(27648 + 36864 + 255) / 256, 256>>>(w1, w2, w3, wf);
    k_prepf<<<Np * 16 / 256, 256>>>(feats);

    dim3 gb(Np / 128, 3);
    k_branch_mma<<<gb, 256, SMEM_CONV>>>(idxs, seg, b1, b2, b3);

    k_normfin<<<12, 256>>>();
    k_hnorm<<<3 * Np * 16 / 256, 256>>>(seg);

    k_final_mma<<<Np / 128, 256, SMEM_CONV>>>(idxs, bf, out);
}

// round 11
// speedup vs baseline: 2.4440x; 1.2765x over previous
#include <cuda_runtime.h>
#include <cuda_fp16.h>
#include <cstdint>

#define Np   262144
#define Bn   4
#define Hn   512
#define Wn   512
#define NINS 16
#define EPSF 1e-5f

// ---------------- device scratch ----------------
__device__ int   g_idx_map[Bn * Hn * Wn];
__device__ float g_h[3u * Np * 64u];              // raw branch outputs fp32
__device__ uint2 g_hn[3u * Np * 16u];             // relu(norm(h)) fp16: 16 uint2/row
__device__ uint2 g_ftH[Np * 16u];                 // feats fp16: 16 uint2/row
__device__ float g_sum [3 * NINS * 64];
__device__ float g_sum2[3 * NINS * 64];
__device__ float g_mean[3 * NINS * 64];
__device__ float g_rinv[3 * NINS * 64];
__device__ int   g_cnt [NINS];
__device__ int   g_ymin[NINS], g_ymax[NINS], g_xmin[NINS], g_xmax[NINS];
__device__ int   g_dil[3 * NINS];
// fp16 fragment-packed weights (proven layout)
__device__ uint2 g_wtbH[3 * 9 * 1024];
__device__ uint2 g_wtfH[36 * 1024];

// ---------------- helpers ----------------
__device__ __forceinline__ void mma_f16(float* d, uint32_t a0, uint32_t a1,
                                        uint32_t a2, uint32_t a3,
                                        uint32_t b0, uint32_t b1) {
    asm volatile(
        "mma.sync.aligned.m16n8k16.row.col.f32.f16.f16.f32 "
        "{%0,%1,%2,%3}, {%4,%5,%6,%7}, {%8,%9}, {%0,%1,%2,%3};"
        : "+f"(d[0]), "+f"(d[1]), "+f"(d[2]), "+f"(d[3])
        : "r"(a0), "r"(a1), "r"(a2), "r"(a3), "r"(b0), "r"(b1));
}

__device__ __forceinline__ uint32_t pack2(float x, float y) {
    __half2 h = __floats2half2_rn(x, y);
    return *(uint32_t*)&h;
}

__device__ __forceinline__ void cp_async8(uint32_t dst, const void* src, int srcsize) {
    asm volatile("cp.async.ca.shared.global [%0], [%1], 8, %2;"
                 :: "r"(dst), "l"(src), "r"(srcsize) : "memory");
}
#define CP_COMMIT() asm volatile("cp.async.commit_group;" ::: "memory")
#define CP_WAIT1()  asm volatile("cp.async.wait_group 1;" ::: "memory")
#define CP_WAIT0()  asm volatile("cp.async.wait_group 0;" ::: "memory")

#define APADH 72
#define SA_BYTES (128 * 144)          // one A buffer: 128 rows x 144 B
#define SA_HALVES (128 * APADH)

// ---------------- init / scatter / dil (proven) ----------------
__global__ void k_init() {
    int i = blockIdx.x * blockDim.x + threadIdx.x;
    if (i < Bn * Hn * Wn) g_idx_map[i] = -1;
    if (i < 3 * NINS * 64) { g_sum[i] = 0.f; g_sum2[i] = 0.f; }
    if (i < NINS) {
        g_cnt[i] = 0;
        g_ymin[i] = 0x7FFFFFFF; g_ymax[i] = 0x80000000;
        g_xmin[i] = 0x7FFFFFFF; g_xmax[i] = 0x80000000;
    }
}

__global__ void k_scatter(const int* __restrict__ idxs, const int* __restrict__ seg) {
    __shared__ int sy0[NINS], sy1[NINS], sx0[NINS], sx1[NINS], sc[NINS];
    int tid = threadIdx.x;
    if (tid < NINS) { sy0[tid] = 0x7FFFFFFF; sy1[tid] = 0x80000000;
                      sx0[tid] = 0x7FFFFFFF; sx1[tid] = 0x80000000; sc[tid] = 0; }
    __syncthreads();
    int i = blockIdx.x * blockDim.x + tid;
    if (i < Np) {
        int b = idxs[3*i], y = idxs[3*i+1], x = idxs[3*i+2];
        g_idx_map[(b * Hn + y) * Wn + x] = i;
        int s = seg[i];
        atomicMin(&sy0[s], y); atomicMax(&sy1[s], y);
        atomicMin(&sx0[s], x); atomicMax(&sx1[s], x);
        atomicAdd(&sc[s], 1);
    }
    __syncthreads();
    if (tid < NINS && sc[tid] > 0) {
        atomicMin(&g_ymin[tid], sy0[tid]); atomicMax(&g_ymax[tid], sy1[tid]);
        atomicMin(&g_xmin[tid], sx0[tid]); atomicMax(&g_xmax[tid], sx1[tid]);
        atomicAdd(&g_cnt[tid], sc[tid]);
    }
}

__global__ void k_dil() {
    int i = threadIdx.x;
    if (i < 3 * NINS) {
        int s = i & 15, r = i >> 4;
        int rate = (r == 0) ? 1 : (r == 1) ? 3 : 5;
        float hr = (float)(g_ymax[s] - g_ymin[s]) / (float)Hn;
        float wr = (float)(g_xmax[s] - g_xmin[s]) / (float)Wn;
        int d = (int)ceilf(fmaxf(hr, wr) * (float)rate);
        if (d < 1) d = 1;
        g_dil[r * NINS + s] = d;
    }
}

// ---------------- weight prep: fp16 fragment pack (proven) ----------------
__global__ void k_prepw(const float* __restrict__ w1, const float* __restrict__ w2,
                        const float* __restrict__ w3, const float* __restrict__ wf)
{
    int i = blockIdx.x * blockDim.x + threadIdx.x;
    if (i < 27648) {
        int br  = i / 9216;
        int r   = i % 9216;
        int tap = r / 1024;
        int r2  = r % 1024;
        int s   = r2 >> 8;
        int col = (r2 >> 2) & 63;
        int tig = r2 & 3;
        int kb  = s * 16 + tig * 2;
        const float* w = (br == 0) ? w1 : (br == 1) ? w2 : w3;
        const float* wt = w + tap * 4096;
        g_wtbH[i] = make_uint2(
            pack2(wt[(kb    ) * 64 + col], wt[(kb + 1) * 64 + col]),
            pack2(wt[(kb + 8) * 64 + col], wt[(kb + 9) * 64 + col]));
    } else if (i < 27648 + 36864) {
        int i2  = i - 27648;
        int u   = i2 / 1024;
        int r2  = i2 % 1024;
        int s   = r2 >> 8;
        int col = (r2 >> 2) & 63;
        int tig = r2 & 3;
        int tap = u >> 2, c = u & 3;
        int kb  = c * 64 + s * 16 + tig * 2;
        const float* wt = wf + (size_t)tap * 256 * 64;
        g_wtfH[i2] = make_uint2(
            pack2(wt[(kb    ) * 64 + col], wt[(kb + 1) * 64 + col]),
            pack2(wt[(kb + 8) * 64 + col], wt[(kb + 9) * 64 + col]));
    }
}

// ---------------- feats -> fp16 pre-convert ----------------
__global__ void __launch_bounds__(256) k_prepf(const float* __restrict__ feats) {
    int i = blockIdx.x * 256 + threadIdx.x;
    float4 f = ((const float4*)feats)[i];
    g_ftH[i] = make_uint2(pack2(f.x, f.y), pack2(f.z, f.w));
}

// ---------------- branch conv + fused stats, cp.async double buffer --------
__global__ void __launch_bounds__(256) k_branch_mma(
    const int* __restrict__ idxs, const int* __restrict__ seg,
    const float* __restrict__ bias1, const float* __restrict__ bias2,
    const float* __restrict__ bias3)
{
    extern __shared__ __half smh[];
    __half* sA   = smh;                              // 2 x [128][72] halves
    int*    snbr = (int*)(smh + 2 * SA_HALVES);      // 128*9

    int tid = threadIdx.x;
    int br  = blockIdx.y;
    int p0  = blockIdx.x * 128;
    const float* bias = (br == 0) ? bias1 : (br == 1) ? bias2 : bias3;

    for (int t = tid; t < 128 * 9; t += 256) {
        int p = t / 9, k = t % 9;
        int gi = p0 + p;
        int b = idxs[3*gi], y = idxs[3*gi+1], x = idxs[3*gi+2];
        int sgi = seg[gi];
        int d = g_dil[br * NINS + sgi];
        int ky = k / 3 - 1, kx = k % 3 - 1;
        int ny = y + ky * d, nx = x + kx * d;
        int nbr = -1;
        if (ny >= 0 && ny < Hn && nx >= 0 && nx < Wn) {
            int n = g_idx_map[(b * Hn + ny) * Wn + nx];
            if (n >= 0 && seg[n] == sgi) nbr = n;
        }
        snbr[t] = nbr;
    }
    __syncthreads();

    int lane = tid & 31, wid = tid >> 5;
    int wm = wid >> 1, wn = wid & 1;
    int gid = lane >> 2, tig = lane & 3;
    int sub = lane >> 4, li = lane & 15;

    uint32_t sA_u = (uint32_t)__cvta_generic_to_shared(sA);

    float acc[2][4][4];
#pragma unroll
    for (int mi = 0; mi < 2; mi++)
#pragma unroll
        for (int ni = 0; ni < 4; ni++)
#pragma unroll
            for (int e = 0; e < 4; e++) acc[mi][ni][e] = 0.f;

    const uint2* wtb = g_wtbH + (size_t)(br * 9) * 1024;

    // prefetch tap 0 into buf 0
    {
        uint32_t base = sA_u;
#pragma unroll
        for (int j = 0; j < 8; j++) {
            int row = wid * 16 + j * 2 + sub;
            int nbr = snbr[row * 9];
            cp_async8(base + row * 144 + li * 8,
                      g_ftH + (size_t)(nbr < 0 ? 0 : nbr) * 16 + li,
                      nbr >= 0 ? 8 : 0);
        }
        CP_COMMIT();
    }

    for (int k = 0; k < 9; k++) {
        if (k < 8) {
            uint32_t base = sA_u + ((k + 1) & 1) * SA_BYTES;
#pragma unroll
            for (int j = 0; j < 8; j++) {
                int row = wid * 16 + j * 2 + sub;
                int nbr = snbr[row * 9 + k + 1];
                cp_async8(base + row * 144 + li * 8,
                          g_ftH + (size_t)(nbr < 0 ? 0 : nbr) * 16 + li,
                          nbr >= 0 ? 8 : 0);
            }
            CP_COMMIT();
            CP_WAIT1();
        } else {
            CP_WAIT0();
        }
        __syncthreads();

        const __half* sAb = sA + (k & 1) * SA_HALVES;
        const uint2* wk = wtb + k * 1024;
#pragma unroll
        for (int s = 0; s < 4; s++) {
            uint32_t a[2][4];
#pragma unroll
            for (int mi = 0; mi < 2; mi++) {
                const __half* ap = sAb + (wm * 32 + mi * 16 + gid) * APADH + s * 16 + tig * 2;
                a[mi][0] = *(const uint32_t*)(ap);
                a[mi][1] = *(const uint32_t*)(ap + 8 * APADH);
                a[mi][2] = *(const uint32_t*)(ap + 8);
                a[mi][3] = *(const uint32_t*)(ap + 8 * APADH + 8);
            }
#pragma unroll
            for (int ni = 0; ni < 4; ni++) {
                uint2 bb = __ldg(wk + (s * 64 + wn * 32 + ni * 8 + gid) * 4 + tig);
                mma_f16(acc[0][ni], a[0][0], a[0][1], a[0][2], a[0][3], bb.x, bb.y);
                mma_f16(acc[1][ni], a[1][0], a[1][1], a[1][2], a[1][3], bb.x, bb.y);
            }
        }
        __syncthreads();
    }

    // add bias, write h
    float* hout = g_h + (size_t)br * Np * 64;
#pragma unroll
    for (int ni = 0; ni < 4; ni++) {
        int col = wn * 32 + ni * 8 + tig * 2;
        float2 bb = *(const float2*)(bias + col);
#pragma unroll
        for (int mi = 0; mi < 2; mi++) {
            acc[mi][ni][0] += bb.x; acc[mi][ni][1] += bb.y;
            acc[mi][ni][2] += bb.x; acc[mi][ni][3] += bb.y;
            int row = p0 + wm * 32 + mi * 16 + gid;
            *(float2*)(hout + (size_t)row * 64 + col) =
                make_float2(acc[mi][ni][0], acc[mi][ni][1]);
            *(float2*)(hout + (size_t)(row + 8) * 64 + col) =
                make_float2(acc[mi][ni][2], acc[mi][ni][3]);
        }
    }

    // fused segment stats
    int sg0 = seg[p0], sg1 = seg[p0 + 127];
    if (sg0 == sg1) {
#pragma unroll
        for (int ni = 0; ni < 4; ni++) {
            float s0 = acc[0][ni][0] + acc[0][ni][2] + acc[1][ni][0] + acc[1][ni][2];
            float s1 = acc[0][ni][1] + acc[0][ni][3] + acc[1][ni][1] + acc[1][ni][3];
            float q0 = acc[0][ni][0]*acc[0][ni][0] + acc[0][ni][2]*acc[0][ni][2]
                     + acc[1][ni][0]*acc[1][ni][0] + acc[1][ni][2]*acc[1][ni][2];
            float q1 = acc[0][ni][1]*acc[0][ni][1] + acc[0][ni][3]*acc[0][ni][3]
                     + acc[1][ni][1]*acc[1][ni][1] + acc[1][ni][3]*acc[1][ni][3];
#pragma unroll
            for (int m = 4; m < 32; m <<= 1) {
                s0 += __shfl_xor_sync(0xFFFFFFFF, s0, m);
                s1 += __shfl_xor_sync(0xFFFFFFFF, s1, m);
                q0 += __shfl_xor_sync(0xFFFFFFFF, q0, m);
                q1 += __shfl_xor_sync(0xFFFFFFFF, q1, m);
            }
            if (gid == 0) {
                int col = wn * 32 + ni * 8 + tig * 2;
                int tb = (br * NINS + sg0) * 64 + col;
                atomicAdd(&g_sum [tb],     s0);
                atomicAdd(&g_sum [tb + 1], s1);
                atomicAdd(&g_sum2[tb],     q0);
                atomicAdd(&g_sum2[tb + 1], q1);
            }
        }
    } else {
#pragma unroll
        for (int ni = 0; ni < 4; ni++) {
            int col = wn * 32 + ni * 8 + tig * 2;
#pragma unroll
            for (int mi = 0; mi < 2; mi++) {
                int rowa = p0 + wm * 32 + mi * 16 + gid;
                int rowb = rowa + 8;
                int sa = seg[rowa], sb = seg[rowb];
                int ta  = (br * NINS + sa) * 64 + col;
                int tb2 = (br * NINS + sb) * 64 + col;
                atomicAdd(&g_sum [ta],      acc[mi][ni][0]);
                atomicAdd(&g_sum [ta + 1],  acc[mi][ni][1]);
                atomicAdd(&g_sum2[ta],      acc[mi][ni][0]*acc[mi][ni][0]);
                atomicAdd(&g_sum2[ta + 1],  acc[mi][ni][1]*acc[mi][ni][1]);
                atomicAdd(&g_sum [tb2],     acc[mi][ni][2]);
                atomicAdd(&g_sum [tb2 + 1], acc[mi][ni][3]);
                atomicAdd(&g_sum2[tb2],     acc[mi][ni][2]*acc[mi][ni][2]);
                atomicAdd(&g_sum2[tb2 + 1], acc[mi][ni][3]*acc[mi][ni][3]);
            }
        }
    }
}

__global__ void k_normfin() {
    int i = blockIdx.x * blockDim.x + threadIdx.x;
    if (i < 3 * NINS * 64) {
        int sgl = (i / 64) % NINS;
        float cnt = (float)g_cnt[sgl];
        float mean = g_sum[i] / cnt;
        float var  = g_sum2[i] / cnt - mean * mean;
        g_mean[i] = mean;
        g_rinv[i] = rsqrtf(var + EPSF);
    }
}

// ---------------- normalize + relu + fp16 pack ----------------
__global__ void __launch_bounds__(256) k_hnorm(const int* __restrict__ seg) {
    int i = blockIdx.x * 256 + threadIdx.x;
    int br  = i / (Np * 16);
    int rem = i % (Np * 16);
    int p   = rem >> 4;
    int c4  = rem & 15;
    int sg  = seg[p];
    float4 hv = ((const float4*)g_h)[i];
    int tb = ((br * NINS + sg) << 6) + c4 * 4;
    float4 mm = *(const float4*)(g_mean + tb);
    float4 rr = *(const float4*)(g_rinv + tb);
    float x0 = fmaxf(0.f, (hv.x - mm.x) * rr.x);
    float x1 = fmaxf(0.f, (hv.y - mm.y) * rr.y);
    float x2 = fmaxf(0.f, (hv.z - mm.z) * rr.z);
    float x3 = fmaxf(0.f, (hv.w - mm.w) * rr.w);
    g_hn[i] = make_uint2(pack2(x0, x1), pack2(x2, x3));
}

// ---------------- final conv: cp.async double buffer ------------------------
__global__ void __launch_bounds__(256) k_final_mma(
    const int* __restrict__ idxs, const float* __restrict__ bf,
    float* __restrict__ out)
{
    extern __shared__ __half smh[];
    __half* sA   = smh;
    int*    snbr = (int*)(smh + 2 * SA_HALVES);

    int tid = threadIdx.x;
    int p0  = blockIdx.x * 128;

    for (int t = tid; t < 128 * 9; t += 256) {
        int p = t / 9, k = t % 9;
        int gi = p0 + p;
        int b = idxs[3*gi], y = idxs[3*gi+1], x = idxs[3*gi+2];
        int ky = k / 3 - 1, kx = k % 3 - 1;
        int ny = y + ky, nx = x + kx;
        int nbr = -1;
        if (ny >= 0 && ny < Hn && nx >= 0 && nx < Wn)
            nbr = g_idx_map[(b * Hn + ny) * Wn + nx];
        snbr[t] = nbr;
    }
    __syncthreads();

    int lane = tid & 31, wid = tid >> 5;
    int wm = wid >> 1, wn = wid & 1;
    int gid = lane >> 2, tig = lane & 3;
    int sub = lane >> 4, li = lane & 15;

    uint32_t sA_u = (uint32_t)__cvta_generic_to_shared(sA);

    float acc[2][4][4];
#pragma unroll
    for (int mi = 0; mi < 2; mi++)
#pragma unroll
        for (int ni = 0; ni < 4; ni++)
#pragma unroll
            for (int e = 0; e < 4; e++) acc[mi][ni][e] = 0.f;

    // prefetch stage 0 (k=0, c=0 -> g_ftH)
    {
        uint32_t base = sA_u;
#pragma unroll
        for (int j = 0; j < 8; j++) {
            int row = wid * 16 + j * 2 + sub;
            int nbr = snbr[row * 9];
            cp_async8(base + row * 144 + li * 8,
                      g_ftH + (size_t)(nbr < 0 ? 0 : nbr) * 16 + li,
                      nbr >= 0 ? 8 : 0);
        }
        CP_COMMIT();
    }

    for (int u = 0; u < 36; u++) {
        if (u < 35) {
            int k2 = (u + 1) >> 2, c2 = (u + 1) & 3;
            const uint2* src2 = (c2 == 0) ? g_ftH : (g_hn + (size_t)(c2 - 1) * Np * 16);
            uint32_t base = sA_u + ((u + 1) & 1) * SA_BYTES;
#pragma unroll
            for (int j = 0; j < 8; j++) {
                int row = wid * 16 + j * 2 + sub;
                int nbr = snbr[row * 9 + k2];
                cp_async8(base + row * 144 + li * 8,
                          src2 + (size_t)(nbr < 0 ? 0 : nbr) * 16 + li,
                          nbr >= 0 ? 8 : 0);
            }
            CP_COMMIT();
            CP_WAIT1();
        } else {
            CP_WAIT0();
        }
        __syncthreads();

        const __half* sAb = sA + (u & 1) * SA_HALVES;
        const uint2* wk = g_wtfH + u * 1024;
#pragma unroll
        for (int s = 0; s < 4; s++) {
            uint32_t a[2][4];
#pragma unroll
            for (int mi = 0; mi < 2; mi++) {
                const __half* ap = sAb + (wm * 32 + mi * 16 + gid) * APADH + s * 16 + tig * 2;
                a[mi][0] = *(const uint32_t*)(ap);
                a[mi][1] = *(const uint32_t*)(ap + 8 * APADH);
                a[mi][2] = *(const uint32_t*)(ap + 8);
                a[mi][3] = *(const uint32_t*)(ap + 8 * APADH + 8);
            }
#pragma unroll
            for (int ni = 0; ni < 4; ni++) {
                uint2 bb = __ldg(wk + (s * 64 + wn * 32 + ni * 8 + gid) * 4 + tig);
                mma_f16(acc[0][ni], a[0][0], a[0][1], a[0][2], a[0][3], bb.x, bb.y);
                mma_f16(acc[1][ni], a[1][0], a[1][1], a[1][2], a[1][3], bb.x, bb.y);
            }
        }
        __syncthreads();
    }

#pragma unroll
    for (int ni = 0; ni < 4; ni++) {
        int col = wn * 32 + ni * 8 + tig * 2;
        float2 bb = *(const float2*)(bf + col);
#pragma unroll
        for (int mi = 0; mi < 2; mi++) {
            int row = p0 + wm * 32 + mi * 16 + gid;
            float2 v0 = make_float2(acc[mi][ni][0] + bb.x, acc[mi][ni][1] + bb.y);
            float2 v1 = make_float2(acc[mi][ni][2] + bb.x, acc[mi][ni][3] + bb.y);
            *(float2*)(out + (size_t)row * 64 + col) = v0;
            *(float2*)(out + (size_t)(row + 8) * 64 + col) = v1;
        }
    }
}

// ---------------- launch ----------------
#define SMEM_CONV (2 * SA_BYTES + 128 * 9 * 4)

extern "C" void kernel_launch(void* const* d_in, const int* in_sizes, int n_in,
                              void* d_out, int out_size)
{
    const float* feats = (const float*)d_in[0];
    const int*   idxs  = (const int*)  d_in[1];
    const int*   seg   = (const int*)  d_in[2];
    const float* w1    = (const float*)d_in[3];
    const float* b1    = (const float*)d_in[4];
    const float* w2    = (const float*)d_in[5];
    const float* b2    = (const float*)d_in[6];
    const float* w3    = (const float*)d_in[7];
    const float* b3    = (const float*)d_in[8];
    const float* wf    = (const float*)d_in[9];
    const float* bf    = (const float*)d_in[10];
    float* out = (float*)d_out;

    cudaFuncSetAttribute(k_branch_mma, cudaFuncAttributeMaxDynamicSharedMemorySize, SMEM_CONV);
    cudaFuncSetAttribute(k_final_mma,  cudaFuncAttributeMaxDynamicSharedMemorySize, SMEM_CONV);

    k_init<<<(Bn * Hn * Wn + 255) / 256, 256>>>();
    k_scatter<<<(Np + 255) / 256, 256>>>(idxs, seg);
    k_dil<<<1, 64>>>();
    k_prepw<<<(27648 + 36864 + 255) / 256, 256>>>(w1, w2, w3, wf);
    k_prepf<<<Np * 16 / 256, 256>>>(feats);

    dim3 gb(Np / 128, 3);
    k_branch_mma<<<gb, 256, SMEM_CONV>>>(idxs, seg, b1, b2, b3);

    k_normfin<<<12, 256>>>();
    k_hnorm<<<3 * Np * 16 / 256, 256>>>(seg);

    k_final_mma<<<Np / 128, 256, SMEM_CONV>>>(idxs, bf, out);
}

// round 12
// speedup vs baseline: 2.5635x; 1.0489x over previous
#include <cuda_runtime.h>
#include <cuda_fp16.h>
#include <cstdint>

#define Np   262144
#define Bn   4
#define Hn   512
#define Wn   512
#define NINS 16
#define EPSF 1e-5f

// ---------------- device scratch ----------------
__device__ int   g_idx_map[Bn * Hn * Wn];
__device__ float g_h[3u * Np * 64u];
__device__ uint2 g_hn[3u * Np * 16u];
__device__ uint2 g_ftH[Np * 16u];
__device__ float g_sum [3 * NINS * 64];
__device__ float g_sum2[3 * NINS * 64];
__device__ float g_mean[3 * NINS * 64];
__device__ float g_rinv[3 * NINS * 64];
__device__ int   g_cnt [NINS];
__device__ int   g_ymin[NINS], g_ymax[NINS], g_xmin[NINS], g_xmax[NINS];
__device__ int   g_dil[3 * NINS];
__device__ uint2 g_wtbH[3 * 9 * 1024];
__device__ uint2 g_wtfH[36 * 1024];

// ---------------- helpers ----------------
__device__ __forceinline__ void mma_f16(float* d, uint32_t a0, uint32_t a1,
                                        uint32_t a2, uint32_t a3,
                                        uint32_t b0, uint32_t b1) {
    asm volatile(
        "mma.sync.aligned.m16n8k16.row.col.f32.f16.f16.f32 "
        "{%0,%1,%2,%3}, {%4,%5,%6,%7}, {%8,%9}, {%0,%1,%2,%3};"
        : "+f"(d[0]), "+f"(d[1]), "+f"(d[2]), "+f"(d[3])
        : "r"(a0), "r"(a1), "r"(a2), "r"(a3), "r"(b0), "r"(b1));
}

__device__ __forceinline__ uint32_t pack2(float x, float y) {
    __half2 h = __floats2half2_rn(x, y);
    return *(uint32_t*)&h;
}

__device__ __forceinline__ void cp_async8(uint32_t dst, const void* src, int srcsize) {
    asm volatile("cp.async.ca.shared.global [%0], [%1], 8, %2;"
                 :: "r"(dst), "l"(src), "r"(srcsize) : "memory");
}
#define CP_COMMIT() asm volatile("cp.async.commit_group;" ::: "memory")
#define CP_WAIT1()  asm volatile("cp.async.wait_group 1;" ::: "memory")
#define CP_WAIT0()  asm volatile("cp.async.wait_group 0;" ::: "memory")

#define ROWS  256                      // rows per block
#define APADH 72
#define SA_BYTES (ROWS * 144)          // one A buffer
#define SA_HALVES (ROWS * APADH)

// ---------------- init / scatter / dil (proven) ----------------
__global__ void k_init() {
    int i = blockIdx.x * blockDim.x + threadIdx.x;
    if (i < Bn * Hn * Wn) g_idx_map[i] = -1;
    if (i < 3 * NINS * 64) { g_sum[i] = 0.f; g_sum2[i] = 0.f; }
    if (i < NINS) {
        g_cnt[i] = 0;
        g_ymin[i] = 0x7FFFFFFF; g_ymax[i] = 0x80000000;
        g_xmin[i] = 0x7FFFFFFF; g_xmax[i] = 0x80000000;
    }
}

__global__ void k_scatter(const int* __restrict__ idxs, const int* __restrict__ seg) {
    __shared__ int sy0[NINS], sy1[NINS], sx0[NINS], sx1[NINS], sc[NINS];
    int tid = threadIdx.x;
    if (tid < NINS) { sy0[tid] = 0x7FFFFFFF; sy1[tid] = 0x80000000;
                      sx0[tid] = 0x7FFFFFFF; sx1[tid] = 0x80000000; sc[tid] = 0; }
    __syncthreads();
    int i = blockIdx.x * blockDim.x + tid;
    if (i < Np) {
        int b = idxs[3*i], y = idxs[3*i+1], x = idxs[3*i+2];
        g_idx_map[(b * Hn + y) * Wn + x] = i;
        int s = seg[i];
        atomicMin(&sy0[s], y); atomicMax(&sy1[s], y);
        atomicMin(&sx0[s], x); atomicMax(&sx1[s], x);
        atomicAdd(&sc[s], 1);
    }
    __syncthreads();
    if (tid < NINS && sc[tid] > 0) {
        atomicMin(&g_ymin[tid], sy0[tid]); atomicMax(&g_ymax[tid], sy1[tid]);
        atomicMin(&g_xmin[tid], sx0[tid]); atomicMax(&g_xmax[tid], sx1[tid]);
        atomicAdd(&g_cnt[tid], sc[tid]);
    }
}

__global__ void k_dil() {
    int i = threadIdx.x;
    if (i < 3 * NINS) {
        int s = i & 15, r = i >> 4;
        int rate = (r == 0) ? 1 : (r == 1) ? 3 : 5;
        float hr = (float)(g_ymax[s] - g_ymin[s]) / (float)Hn;
        float wr = (float)(g_xmax[s] - g_xmin[s]) / (float)Wn;
        int d = (int)ceilf(fmaxf(hr, wr) * (float)rate);
        if (d < 1) d = 1;
        g_dil[r * NINS + s] = d;
    }
}

// ---------------- weight prep (proven) ----------------
__global__ void k_prepw(const float* __restrict__ w1, const float* __restrict__ w2,
                        const float* __restrict__ w3, const float* __restrict__ wf)
{
    int i = blockIdx.x * blockDim.x + threadIdx.x;
    if (i < 27648) {
        int br  = i / 9216;
        int r   = i % 9216;
        int tap = r / 1024;
        int r2  = r % 1024;
        int s   = r2 >> 8;
        int col = (r2 >> 2) & 63;
        int tig = r2 & 3;
        int kb  = s * 16 + tig * 2;
        const float* w = (br == 0) ? w1 : (br == 1) ? w2 : w3;
        const float* wt = w + tap * 4096;
        g_wtbH[i] = make_uint2(
            pack2(wt[(kb    ) * 64 + col], wt[(kb + 1) * 64 + col]),
            pack2(wt[(kb + 8) * 64 + col], wt[(kb + 9) * 64 + col]));
    } else if (i < 27648 + 36864) {
        int i2  = i - 27648;
        int u   = i2 / 1024;
        int r2  = i2 % 1024;
        int s   = r2 >> 8;
        int col = (r2 >> 2) & 63;
        int tig = r2 & 3;
        int tap = u >> 2, c = u & 3;
        int kb  = c * 64 + s * 16 + tig * 2;
        const float* wt = wf + (size_t)tap * 256 * 64;
        g_wtfH[i2] = make_uint2(
            pack2(wt[(kb    ) * 64 + col], wt[(kb + 1) * 64 + col]),
            pack2(wt[(kb + 8) * 64 + col], wt[(kb + 9) * 64 + col]));
    }
}

// ---------------- feats -> fp16 pre-convert ----------------
__global__ void __launch_bounds__(256) k_prepf(const float* __restrict__ feats) {
    int i = blockIdx.x * 256 + threadIdx.x;
    float4 f = ((const float4*)feats)[i];
    g_ftH[i] = make_uint2(pack2(f.x, f.y), pack2(f.z, f.w));
}

// ---------------- branch conv + fused stats: 256-row blocks, 64x32 warps ---
__global__ void __launch_bounds__(256, 2) k_branch_mma(
    const int* __restrict__ idxs, const int* __restrict__ seg,
    const float* __restrict__ bias1, const float* __restrict__ bias2,
    const float* __restrict__ bias3)
{
    extern __shared__ __half smh[];
    __half* sA   = smh;                              // 2 x [256][72] halves
    int*    snbr = (int*)(smh + 2 * SA_HALVES);      // 256*9

    int tid = threadIdx.x;
    int br  = blockIdx.y;
    int p0  = blockIdx.x * ROWS;
    const float* bias = (br == 0) ? bias1 : (br == 1) ? bias2 : bias3;

    for (int t = tid; t < ROWS * 9; t += 256) {
        int p = t / 9, k = t % 9;
        int gi = p0 + p;
        int b = idxs[3*gi], y = idxs[3*gi+1], x = idxs[3*gi+2];
        int sgi = seg[gi];
        int d = g_dil[br * NINS + sgi];
        int ky = k / 3 - 1, kx = k % 3 - 1;
        int ny = y + ky * d, nx = x + kx * d;
        int nbr = -1;
        if (ny >= 0 && ny < Hn && nx >= 0 && nx < Wn) {
            int n = g_idx_map[(b * Hn + ny) * Wn + nx];
            if (n >= 0 && seg[n] == sgi) nbr = n;
        }
        snbr[t] = nbr;
    }
    __syncthreads();

    int lane = tid & 31, wid = tid >> 5;
    int wm = wid >> 1, wn = wid & 1;            // 4 x 2 grid, warp tile 64x32
    int gid = lane >> 2, tig = lane & 3;
    int sub = lane >> 4, li = lane & 15;

    uint32_t sA_u = (uint32_t)__cvta_generic_to_shared(sA);

    float acc[4][4][4];
#pragma unroll
    for (int mi = 0; mi < 4; mi++)
#pragma unroll
        for (int ni = 0; ni < 4; ni++)
#pragma unroll
            for (int e = 0; e < 4; e++) acc[mi][ni][e] = 0.f;

    const uint2* wtb = g_wtbH + (size_t)(br * 9) * 1024;

    // prefetch tap 0 (each warp fills 32 rows: 16 iters x 2 rows)
    {
        uint32_t base = sA_u;
#pragma unroll
        for (int j = 0; j < 16; j++) {
            int row = wid * 32 + j * 2 + sub;
            int nbr = snbr[row * 9];
            cp_async8(base + row * 144 + li * 8,
                      g_ftH + (size_t)(nbr < 0 ? 0 : nbr) * 16 + li,
                      nbr >= 0 ? 8 : 0);
        }
        CP_COMMIT();
    }

    for (int k = 0; k < 9; k++) {
        if (k < 8) {
            uint32_t base = sA_u + ((k + 1) & 1) * SA_BYTES;
#pragma unroll
            for (int j = 0; j < 16; j++) {
                int row = wid * 32 + j * 2 + sub;
                int nbr = snbr[row * 9 + k + 1];
                cp_async8(base + row * 144 + li * 8,
                          g_ftH + (size_t)(nbr < 0 ? 0 : nbr) * 16 + li,
                          nbr >= 0 ? 8 : 0);
            }
            CP_COMMIT();
            CP_WAIT1();
        } else {
            CP_WAIT0();
        }
        __syncthreads();

        const __half* sAb = sA + (k & 1) * SA_HALVES;
        const uint2* wk = wtb + k * 1024;
#pragma unroll
        for (int s = 0; s < 4; s++) {
            uint32_t a[4][4];
#pragma unroll
            for (int mi = 0; mi < 4; mi++) {
                const __half* ap = sAb + (wm * 64 + mi * 16 + gid) * APADH + s * 16 + tig * 2;
                a[mi][0] = *(const uint32_t*)(ap);
                a[mi][1] = *(const uint32_t*)(ap + 8 * APADH);
                a[mi][2] = *(const uint32_t*)(ap + 8);
                a[mi][3] = *(const uint32_t*)(ap + 8 * APADH + 8);
            }
#pragma unroll
            for (int ni = 0; ni < 4; ni++) {
                uint2 bb = __ldg(wk + (s * 64 + wn * 32 + ni * 8 + gid) * 4 + tig);
#pragma unroll
                for (int mi = 0; mi < 4; mi++)
                    mma_f16(acc[mi][ni], a[mi][0], a[mi][1], a[mi][2], a[mi][3], bb.x, bb.y);
            }
        }
        __syncthreads();
    }

    // add bias, write h
    float* hout = g_h + (size_t)br * Np * 64;
#pragma unroll
    for (int ni = 0; ni < 4; ni++) {
        int col = wn * 32 + ni * 8 + tig * 2;
        float2 bb = *(const float2*)(bias + col);
#pragma unroll
        for (int mi = 0; mi < 4; mi++) {
            acc[mi][ni][0] += bb.x; acc[mi][ni][1] += bb.y;
            acc[mi][ni][2] += bb.x; acc[mi][ni][3] += bb.y;
            int row = p0 + wm * 64 + mi * 16 + gid;
            *(float2*)(hout + (size_t)row * 64 + col) =
                make_float2(acc[mi][ni][0], acc[mi][ni][1]);
            *(float2*)(hout + (size_t)(row + 8) * 64 + col) =
                make_float2(acc[mi][ni][2], acc[mi][ni][3]);
        }
    }

    // fused segment stats
    int sg0 = seg[p0], sg1 = seg[p0 + ROWS - 1];
    if (sg0 == sg1) {
#pragma unroll
        for (int ni = 0; ni < 4; ni++) {
            float s0 = 0.f, s1 = 0.f, q0 = 0.f, q1 = 0.f;
#pragma unroll
            for (int mi = 0; mi < 4; mi++) {
                s0 += acc[mi][ni][0] + acc[mi][ni][2];
                s1 += acc[mi][ni][1] + acc[mi][ni][3];
                q0 += acc[mi][ni][0]*acc[mi][ni][0] + acc[mi][ni][2]*acc[mi][ni][2];
                q1 += acc[mi][ni][1]*acc[mi][ni][1] + acc[mi][ni][3]*acc[mi][ni][3];
            }
#pragma unroll
            for (int m = 4; m < 32; m <<= 1) {
                s0 += __shfl_xor_sync(0xFFFFFFFF, s0, m);
                s1 += __shfl_xor_sync(0xFFFFFFFF, s1, m);
                q0 += __shfl_xor_sync(0xFFFFFFFF, q0, m);
                q1 += __shfl_xor_sync(0xFFFFFFFF, q1, m);
            }
            if (gid == 0) {
                int col = wn * 32 + ni * 8 + tig * 2;
                int tb = (br * NINS + sg0) * 64 + col;
                atomicAdd(&g_sum [tb],     s0);
                atomicAdd(&g_sum [tb + 1], s1);
                atomicAdd(&g_sum2[tb],     q0);
                atomicAdd(&g_sum2[tb + 1], q1);
            }
        }
    } else {
#pragma unroll
        for (int ni = 0; ni < 4; ni++) {
            int col = wn * 32 + ni * 8 + tig * 2;
#pragma unroll
            for (int mi = 0; mi < 4; mi++) {
                int rowa = p0 + wm * 64 + mi * 16 + gid;
                int rowb = rowa + 8;
                int sa = seg[rowa], sb = seg[rowb];
                int ta  = (br * NINS + sa) * 64 + col;
                int tb2 = (br * NINS + sb) * 64 + col;
                atomicAdd(&g_sum [ta],      acc[mi][ni][0]);
                atomicAdd(&g_sum [ta + 1],  acc[mi][ni][1]);
                atomicAdd(&g_sum2[ta],      acc[mi][ni][0]*acc[mi][ni][0]);
                atomicAdd(&g_sum2[ta + 1],  acc[mi][ni][1]*acc[mi][ni][1]);
                atomicAdd(&g_sum [tb2],     acc[mi][ni][2]);
                atomicAdd(&g_sum [tb2 + 1], acc[mi][ni][3]);
                atomicAdd(&g_sum2[tb2],     acc[mi][ni][2]*acc[mi][ni][2]);
                atomicAdd(&g_sum2[tb2 + 1], acc[mi][ni][3]*acc[mi][ni][3]);
            }
        }
    }
}

__global__ void k_normfin() {
    int i = blockIdx.x * blockDim.x + threadIdx.x;
    if (i < 3 * NINS * 64) {
        int sgl = (i / 64) % NINS;
        float cnt = (float)g_cnt[sgl];
        float mean = g_sum[i] / cnt;
        float var  = g_sum2[i] / cnt - mean * mean;
        g_mean[i] = mean;
        g_rinv[i] = rsqrtf(var + EPSF);
    }
}

// ---------------- normalize + relu + fp16 pack ----------------
__global__ void __launch_bounds__(256) k_hnorm(const int* __restrict__ seg) {
    int i = blockIdx.x * 256 + threadIdx.x;
    int br  = i / (Np * 16);
    int rem = i % (Np * 16);
    int p   = rem >> 4;
    int c4  = rem & 15;
    int sg  = seg[p];
    float4 hv = ((const float4*)g_h)[i];
    int tb = ((br * NINS + sg) << 6) + c4 * 4;
    float4 mm = *(const float4*)(g_mean + tb);
    float4 rr = *(const float4*)(g_rinv + tb);
    float x0 = fmaxf(0.f, (hv.x - mm.x) * rr.x);
    float x1 = fmaxf(0.f, (hv.y - mm.y) * rr.y);
    float x2 = fmaxf(0.f, (hv.z - mm.z) * rr.z);
    float x3 = fmaxf(0.f, (hv.w - mm.w) * rr.w);
    g_hn[i] = make_uint2(pack2(x0, x1), pack2(x2, x3));
}

// ---------------- final conv: 256-row blocks, 64x32 warps ------------------
__global__ void __launch_bounds__(256, 2) k_final_mma(
    const int* __restrict__ idxs, const float* __restrict__ bf,
    float* __restrict__ out)
{
    extern __shared__ __half smh[];
    __half* sA   = smh;
    int*    snbr = (int*)(smh + 2 * SA_HALVES);

    int tid = threadIdx.x;
    int p0  = blockIdx.x * ROWS;

    for (int t = tid; t < ROWS * 9; t += 256) {
        int p = t / 9, k = t % 9;
        int gi = p0 + p;
        int b = idxs[3*gi], y = idxs[3*gi+1], x = idxs[3*gi+2];
        int ky = k / 3 - 1, kx = k % 3 - 1;
        int ny = y + ky, nx = x + kx;
        int nbr = -1;
        if (ny >= 0 && ny < Hn && nx >= 0 && nx < Wn)
            nbr = g_idx_map[(b * Hn + ny) * Wn + nx];
        snbr[t] = nbr;
    }
    __syncthreads();

    int lane = tid & 31, wid = tid >> 5;
    int wm = wid >> 1, wn = wid & 1;
    int gid = lane >> 2, tig = lane & 3;
    int sub = lane >> 4, li = lane & 15;

    uint32_t sA_u = (uint32_t)__cvta_generic_to_shared(sA);

    float acc[4][4][4];
#pragma unroll
    for (int mi = 0; mi < 4; mi++)
#pragma unroll
        for (int ni = 0; ni < 4; ni++)
#pragma unroll
            for (int e = 0; e < 4; e++) acc[mi][ni][e] = 0.f;

    // prefetch stage 0
    {
        uint32_t base = sA_u;
#pragma unroll
        for (int j = 0; j < 16; j++) {
            int row = wid * 32 + j * 2 + sub;
            int nbr = snbr[row * 9];
            cp_async8(base + row * 144 + li * 8,
                      g_ftH + (size_t)(nbr < 0 ? 0 : nbr) * 16 + li,
                      nbr >= 0 ? 8 : 0);
        }
        CP_COMMIT();
    }

    for (int u = 0; u < 36; u++) {
        if (u < 35) {
            int k2 = (u + 1) >> 2, c2 = (u + 1) & 3;
            const uint2* src2 = (c2 == 0) ? g_ftH : (g_hn + (size_t)(c2 - 1) * Np * 16);
            uint32_t base = sA_u + ((u + 1) & 1) * SA_BYTES;
#pragma unroll
            for (int j = 0; j < 16; j++) {
                int row = wid * 32 + j * 2 + sub;
                int nbr = snbr[row * 9 + k2];
                cp_async8(base + row * 144 + li * 8,
                          src2 + (size_t)(nbr < 0 ? 0 : nbr) * 16 + li,
                          nbr >= 0 ? 8 : 0);
            }
            CP_COMMIT();
            CP_WAIT1();
        } else {
            CP_WAIT0();
        }
        __syncthreads();

        const __half* sAb = sA + (u & 1) * SA_HALVES;
        const uint2* wk = g_wtfH + u * 1024;
#pragma unroll
        for (int s = 0; s < 4; s++) {
            uint32_t a[4][4];
#pragma unroll
            for (int mi = 0; mi < 4; mi++) {
                const __half* ap = sAb + (wm * 64 + mi * 16 + gid) * APADH + s * 16 + tig * 2;
                a[mi][0] = *(const uint32_t*)(ap);
                a[mi][1] = *(const uint32_t*)(ap + 8 * APADH);
                a[mi][2] = *(const uint32_t*)(ap + 8);
                a[mi][3] = *(const uint32_t*)(ap + 8 * APADH + 8);
            }
#pragma unroll
            for (int ni = 0; ni < 4; ni++) {
                uint2 bb = __ldg(wk + (s * 64 + wn * 32 + ni * 8 + gid) * 4 + tig);
#pragma unroll
                for (int mi = 0; mi < 4; mi++)
                    mma_f16(acc[mi][ni], a[mi][0], a[mi][1], a[mi][2], a[mi][3], bb.x, bb.y);
            }
        }
        __syncthreads();
    }

#pragma unroll
    for (int ni = 0; ni < 4; ni++) {
        int col = wn * 32 + ni * 8 + tig * 2;
        float2 bb = *(const float2*)(bf + col);
#pragma unroll
        for (int mi = 0; mi < 4; mi++) {
            int row = p0 + wm * 64 + mi * 16 + gid;
            float2 v0 = make_float2(acc[mi][ni][0] + bb.x, acc[mi][ni][1] + bb.y);
            float2 v1 = make_float2(acc[mi][ni][2] + bb.x, acc[mi][ni][3] + bb.y);
            *(float2*)(out + (size_t)row * 64 + col) = v0;
            *(float2*)(out + (size_t)(row + 8) * 64 + col) = v1;
        }
    }
}

// ---------------- launch ----------------
#define SMEM_CONV (2 * SA_BYTES + ROWS * 9 * 4)

extern "C" void kernel_launch(void* const* d_in, const int* in_sizes, int n_in,
                              void* d_out, int out_size)
{
    const float* feats = (const float*)d_in[0];
    const int*   idxs  = (const int*)  d_in[1];
    const int*   seg   = (const int*)  d_in[2];
    const float* w1    = (const float*)d_in[3];
    const float* b1    = (const float*)d_in[4];
    const float* w2    = (const float*)d_in[5];
    const float* b2    = (const float*)d_in[6];
    const float* w3    = (const float*)d_in[7];
    const float* b3    = (const float*)d_in[8];
    const float* wf    = (const float*)d_in[9];
    const float* bf    = (const float*)d_in[10];
    float* out = (float*)d_out;

    cudaFuncSetAttribute(k_branch_mma, cudaFuncAttributeMaxDynamicSharedMemorySize, SMEM_CONV);
    cudaFuncSetAttribute(k_final_mma,  cudaFuncAttributeMaxDynamicSharedMemorySize, SMEM_CONV);

    k_init<<<(Bn * Hn * Wn + 255) / 256, 256>>>();
    k_scatter<<<(Np + 255) / 256, 256>>>(idxs, seg);
    k_dil<<<1, 64>>>();
    k_prepw<<<(27648 + 36864 + 255) / 256, 256>>>(w1, w2, w3, wf);
    k_prepf<<<Np * 16 / 256, 256>>>(feats);

    dim3 gb(Np / ROWS, 3);
    k_branch_mma<<<gb, 256, SMEM_CONV>>>(idxs, seg, b1, b2, b3);

    k_normfin<<<12, 256>>>();
    k_hnorm<<<3 * Np * 16 / 256, 256>>>(seg);

    k_final_mma<<<Np / ROWS, 256, SMEM_CONV>>>(idxs, bf, out);
}

// round 13
// speedup vs baseline: 2.7356x; 1.0671x over previous
#include <cuda_runtime.h>
#include <cuda_fp16.h>
#include <cstdint>

#define Np   262144
#define Bn   4
#define Hn   512
#define Wn   512
#define NINS 16
#define EPSF 1e-5f

// ---------------- device scratch ----------------
__device__ int      g_idx_map[Bn * Hn * Wn];
__device__ uint32_t g_hraw[3u * Np * 32u];        // raw h (bias added) fp16: 32 uint32/row
__device__ uint2    g_hn[3u * Np * 16u];          // relu(norm(h)) fp16
__device__ uint2    g_ftH[Np * 16u];              // feats fp16
__device__ float g_sum [3 * NINS * 64];
__device__ float g_sum2[3 * NINS * 64];
__device__ float g_mean[3 * NINS * 64];
__device__ float g_rinv[3 * NINS * 64];
__device__ int   g_cnt [NINS];
__device__ int   g_ymin[NINS], g_ymax[NINS], g_xmin[NINS], g_xmax[NINS];
__device__ int   g_dil[3 * NINS];
__device__ uint2 g_wtbH[3 * 9 * 1024];
__device__ uint2 g_wtfH[36 * 1024];

// ---------------- helpers ----------------
__device__ __forceinline__ void mma_f16(float* d, uint32_t a0, uint32_t a1,
                                        uint32_t a2, uint32_t a3,
                                        uint32_t b0, uint32_t b1) {
    asm volatile(
        "mma.sync.aligned.m16n8k16.row.col.f32.f16.f16.f32 "
        "{%0,%1,%2,%3}, {%4,%5,%6,%7}, {%8,%9}, {%0,%1,%2,%3};"
        : "+f"(d[0]), "+f"(d[1]), "+f"(d[2]), "+f"(d[3])
        : "r"(a0), "r"(a1), "r"(a2), "r"(a3), "r"(b0), "r"(b1));
}

__device__ __forceinline__ void ldsm_x4(uint32_t* r, uint32_t addr) {
    asm volatile("ldmatrix.sync.aligned.m8n8.x4.shared.b16 {%0,%1,%2,%3}, [%4];"
                 : "=r"(r[0]), "=r"(r[1]), "=r"(r[2]), "=r"(r[3]) : "r"(addr));
}

__device__ __forceinline__ uint32_t pack2(float x, float y) {
    __half2 h = __floats2half2_rn(x, y);
    return *(uint32_t*)&h;
}

__device__ __forceinline__ void cp_async8(uint32_t dst, const void* src, int srcsize) {
    asm volatile("cp.async.ca.shared.global [%0], [%1], 8, %2;"
                 :: "r"(dst), "l"(src), "r"(srcsize) : "memory");
}
#define CP_COMMIT() asm volatile("cp.async.commit_group;" ::: "memory")
#define CP_WAIT1()  asm volatile("cp.async.wait_group 1;" ::: "memory")
#define CP_WAIT0()  asm volatile("cp.async.wait_group 0;" ::: "memory")

#define ROWS  256
#define APADH 72
#define SA_BYTES (ROWS * 144)
#define SA_HALVES (ROWS * APADH)

// ---------------- init / scatter / dil (proven) ----------------
__global__ void k_init() {
    int i = blockIdx.x * blockDim.x + threadIdx.x;
    if (i < Bn * Hn * Wn) g_idx_map[i] = -1;
    if (i < 3 * NINS * 64) { g_sum[i] = 0.f; g_sum2[i] = 0.f; }
    if (i < NINS) {
        g_cnt[i] = 0;
        g_ymin[i] = 0x7FFFFFFF; g_ymax[i] = 0x80000000;
        g_xmin[i] = 0x7FFFFFFF; g_xmax[i] = 0x80000000;
    }
}

__global__ void k_scatter(const int* __restrict__ idxs, const int* __restrict__ seg) {
    __shared__ int sy0[NINS], sy1[NINS], sx0[NINS], sx1[NINS], sc[NINS];
    int tid = threadIdx.x;
    if (tid < NINS) { sy0[tid] = 0x7FFFFFFF; sy1[tid] = 0x80000000;
                      sx0[tid] = 0x7FFFFFFF; sx1[tid] = 0x80000000; sc[tid] = 0; }
    __syncthreads();
    int i = blockIdx.x * blockDim.x + tid;
    if (i < Np) {
        int b = idxs[3*i], y = idxs[3*i+1], x = idxs[3*i+2];
        g_idx_map[(b * Hn + y) * Wn + x] = i;
        int s = seg[i];
        atomicMin(&sy0[s], y); atomicMax(&sy1[s], y);
        atomicMin(&sx0[s], x); atomicMax(&sx1[s], x);
        atomicAdd(&sc[s], 1);
    }
    __syncthreads();
    if (tid < NINS && sc[tid] > 0) {
        atomicMin(&g_ymin[tid], sy0[tid]); atomicMax(&g_ymax[tid], sy1[tid]);
        atomicMin(&g_xmin[tid], sx0[tid]); atomicMax(&g_xmax[tid], sx1[tid]);
        atomicAdd(&g_cnt[tid], sc[tid]);
    }
}

__global__ void k_dil() {
    int i = threadIdx.x;
    if (i < 3 * NINS) {
        int s = i & 15, r = i >> 4;
        int rate = (r == 0) ? 1 : (r == 1) ? 3 : 5;
        float hr = (float)(g_ymax[s] - g_ymin[s]) / (float)Hn;
        float wr = (float)(g_xmax[s] - g_xmin[s]) / (float)Wn;
        int d = (int)ceilf(fmaxf(hr, wr) * (float)rate);
        if (d < 1) d = 1;
        g_dil[r * NINS + s] = d;
    }
}

// ---------------- weight prep (proven) ----------------
__global__ void k_prepw(const float* __restrict__ w1, const float* __restrict__ w2,
                        const float* __restrict__ w3, const float* __restrict__ wf)
{
    int i = blockIdx.x * blockDim.x + threadIdx.x;
    if (i < 27648) {
        int br  = i / 9216;
        int r   = i % 9216;
        int tap = r / 1024;
        int r2  = r % 1024;
        int s   = r2 >> 8;
        int col = (r2 >> 2) & 63;
        int tig = r2 & 3;
        int kb  = s * 16 + tig * 2;
        const float* w = (br == 0) ? w1 : (br == 1) ? w2 : w3;
        const float* wt = w + tap * 4096;
        g_wtbH[i] = make_uint2(
            pack2(wt[(kb    ) * 64 + col], wt[(kb + 1) * 64 + col]),
            pack2(wt[(kb + 8) * 64 + col], wt[(kb + 9) * 64 + col]));
    } else if (i < 27648 + 36864) {
        int i2  = i - 27648;
        int u   = i2 / 1024;
        int r2  = i2 % 1024;
        int s   = r2 >> 8;
        int col = (r2 >> 2) & 63;
        int tig = r2 & 3;
        int tap = u >> 2, c = u & 3;
        int kb  = c * 64 + s * 16 + tig * 2;
        const float* wt = wf + (size_t)tap * 256 * 64;
        g_wtfH[i2] = make_uint2(
            pack2(wt[(kb    ) * 64 + col], wt[(kb + 1) * 64 + col]),
            pack2(wt[(kb + 8) * 64 + col], wt[(kb + 9) * 64 + col]));
    }
}

// ---------------- feats -> fp16 pre-convert ----------------
__global__ void __launch_bounds__(256) k_prepf(const float* __restrict__ feats) {
    int i = blockIdx.x * 256 + threadIdx.x;
    float4 f = ((const float4*)feats)[i];
    g_ftH[i] = make_uint2(pack2(f.x, f.y), pack2(f.z, f.w));
}

// ---------------- branch conv + fused stats ----------------
__global__ void __launch_bounds__(256, 2) k_branch_mma(
    const int* __restrict__ idxs, const int* __restrict__ seg,
    const float* __restrict__ bias1, const float* __restrict__ bias2,
    const float* __restrict__ bias3)
{
    extern __shared__ __half smh[];
    __half* sA   = smh;
    int*    snbr = (int*)(smh + 2 * SA_HALVES);

    int tid = threadIdx.x;
    int br  = blockIdx.y;
    int p0  = blockIdx.x * ROWS;
    const float* bias = (br == 0) ? bias1 : (br == 1) ? bias2 : bias3;

    for (int t = tid; t < ROWS * 9; t += 256) {
        int p = t / 9, k = t % 9;
        int gi = p0 + p;
        int b = idxs[3*gi], y = idxs[3*gi+1], x = idxs[3*gi+2];
        int sgi = seg[gi];
        int d = g_dil[br * NINS + sgi];
        int ky = k / 3 - 1, kx = k % 3 - 1;
        int ny = y + ky * d, nx = x + kx * d;
        int nbr = -1;
        if (ny >= 0 && ny < Hn && nx >= 0 && nx < Wn) {
            int n = g_idx_map[(b * Hn + ny) * Wn + nx];
            if (n >= 0 && seg[n] == sgi) nbr = n;
        }
        snbr[t] = nbr;
    }
    __syncthreads();

    int lane = tid & 31, wid = tid >> 5;
    int wm = wid >> 1, wn = wid & 1;
    int gid = lane >> 2, tig = lane & 3;
    int sub = lane >> 4, li = lane & 15;

    uint32_t sA_u = (uint32_t)__cvta_generic_to_shared(sA);
    // ldmatrix per-lane address components
    int lrow = lane & 15, lkh = lane >> 4;

    float acc[4][4][4];
#pragma unroll
    for (int mi = 0; mi < 4; mi++)
#pragma unroll
        for (int ni = 0; ni < 4; ni++)
#pragma unroll
            for (int e = 0; e < 4; e++) acc[mi][ni][e] = 0.f;

    const uint2* wtb = g_wtbH + (size_t)(br * 9) * 1024;

    {
        uint32_t base = sA_u;
#pragma unroll
        for (int j = 0; j < 16; j++) {
            int row = wid * 32 + j * 2 + sub;
            int nbr = snbr[row * 9];
            cp_async8(base + row * 144 + li * 8,
                      g_ftH + (size_t)(nbr < 0 ? 0 : nbr) * 16 + li,
                      nbr >= 0 ? 8 : 0);
        }
        CP_COMMIT();
    }

    for (int k = 0; k < 9; k++) {
        if (k < 8) {
            uint32_t base = sA_u + ((k + 1) & 1) * SA_BYTES;
#pragma unroll
            for (int j = 0; j < 16; j++) {
                int row = wid * 32 + j * 2 + sub;
                int nbr = snbr[row * 9 + k + 1];
                cp_async8(base + row * 144 + li * 8,
                          g_ftH + (size_t)(nbr < 0 ? 0 : nbr) * 16 + li,
                          nbr >= 0 ? 8 : 0);
            }
            CP_COMMIT();
            CP_WAIT1();
        } else {
            CP_WAIT0();
        }
        __syncthreads();

        uint32_t sAb_u = sA_u + (k & 1) * SA_BYTES;
        const uint2* wk = wtb + k * 1024;
#pragma unroll
        for (int s = 0; s < 4; s++) {
            uint32_t a[4][4];
#pragma unroll
            for (int mi = 0; mi < 4; mi++) {
                uint32_t addr = sAb_u + (wm * 64 + mi * 16 + lrow) * 144 + s * 32 + lkh * 16;
                ldsm_x4(a[mi], addr);
            }
#pragma unroll
            for (int ni = 0; ni < 4; ni++) {
                uint2 bb = __ldg(wk + (s * 64 + wn * 32 + ni * 8 + gid) * 4 + tig);
#pragma unroll
                for (int mi = 0; mi < 4; mi++)
                    mma_f16(acc[mi][ni], a[mi][0], a[mi][1], a[mi][2], a[mi][3], bb.x, bb.y);
            }
        }
        __syncthreads();
    }

    // add bias, write raw h as fp16
    uint32_t* hout = g_hraw + (size_t)br * Np * 32;
#pragma unroll
    for (int ni = 0; ni < 4; ni++) {
        int col = wn * 32 + ni * 8 + tig * 2;
        float2 bb = *(const float2*)(bias + col);
#pragma unroll
        for (int mi = 0; mi < 4; mi++) {
            acc[mi][ni][0] += bb.x; acc[mi][ni][1] += bb.y;
            acc[mi][ni][2] += bb.x; acc[mi][ni][3] += bb.y;
            int row = p0 + wm * 64 + mi * 16 + gid;
            hout[(size_t)row * 32 + (col >> 1)] = pack2(acc[mi][ni][0], acc[mi][ni][1]);
            hout[(size_t)(row + 8) * 32 + (col >> 1)] = pack2(acc[mi][ni][2], acc[mi][ni][3]);
        }
    }

    // fused segment stats (fp32, exact)
    int sg0 = seg[p0], sg1 = seg[p0 + ROWS - 1];
    if (sg0 == sg1) {
#pragma unroll
        for (int ni = 0; ni < 4; ni++) {
            float s0 = 0.f, s1 = 0.f, q0 = 0.f, q1 = 0.f;
#pragma unroll
            for (int mi = 0; mi < 4; mi++) {
                s0 += acc[mi][ni][0] + acc[mi][ni][2];
                s1 += acc[mi][ni][1] + acc[mi][ni][3];
                q0 += acc[mi][ni][0]*acc[mi][ni][0] + acc[mi][ni][2]*acc[mi][ni][2];
                q1 += acc[mi][ni][1]*acc[mi][ni][1] + acc[mi][ni][3]*acc[mi][ni][3];
            }
#pragma unroll
            for (int m = 4; m < 32; m <<= 1) {
                s0 += __shfl_xor_sync(0xFFFFFFFF, s0, m);
                s1 += __shfl_xor_sync(0xFFFFFFFF, s1, m);
                q0 += __shfl_xor_sync(0xFFFFFFFF, q0, m);
                q1 += __shfl_xor_sync(0xFFFFFFFF, q1, m);
            }
            if (gid == 0) {
                int col = wn * 32 + ni * 8 + tig * 2;
                int tb = (br * NINS + sg0) * 64 + col;
                atomicAdd(&g_sum [tb],     s0);
                atomicAdd(&g_sum [tb + 1], s1);
                atomicAdd(&g_sum2[tb],     q0);
                atomicAdd(&g_sum2[tb + 1], q1);
            }
        }
    } else {
#pragma unroll
        for (int ni = 0; ni < 4; ni++) {
            int col = wn * 32 + ni * 8 + tig * 2;
#pragma unroll
            for (int mi = 0; mi < 4; mi++) {
                int rowa = p0 + wm * 64 + mi * 16 + gid;
                int rowb = rowa + 8;
                int sa = seg[rowa], sb = seg[rowb];
                int ta  = (br * NINS + sa) * 64 + col;
                int tb2 = (br * NINS + sb) * 64 + col;
                atomicAdd(&g_sum [ta],      acc[mi][ni][0]);
                atomicAdd(&g_sum [ta + 1],  acc[mi][ni][1]);
                atomicAdd(&g_sum2[ta],      acc[mi][ni][0]*acc[mi][ni][0]);
                atomicAdd(&g_sum2[ta + 1],  acc[mi][ni][1]*acc[mi][ni][1]);
                atomicAdd(&g_sum [tb2],     acc[mi][ni][2]);
                atomicAdd(&g_sum [tb2 + 1], acc[mi][ni][3]);
                atomicAdd(&g_sum2[tb2],     acc[mi][ni][2]*acc[mi][ni][2]);
                atomicAdd(&g_sum2[tb2 + 1], acc[mi][ni][3]*acc[mi][ni][3]);
            }
        }
    }
}

__global__ void k_normfin() {
    int i = blockIdx.x * blockDim.x + threadIdx.x;
    if (i < 3 * NINS * 64) {
        int sgl = (i / 64) % NINS;
        float cnt = (float)g_cnt[sgl];
        float mean = g_sum[i] / cnt;
        float var  = g_sum2[i] / cnt - mean * mean;
        g_mean[i] = mean;
        g_rinv[i] = rsqrtf(var + EPSF);
    }
}

// ---------------- normalize + relu (fp16 in, fp16 out) ----------------
__global__ void __launch_bounds__(256) k_hnorm(const int* __restrict__ seg) {
    int i = blockIdx.x * 256 + threadIdx.x;      // 3*Np*16 uint2 units
    int br  = i / (Np * 16);
    int rem = i % (Np * 16);
    int p   = rem >> 4;
    int c4  = rem & 15;
    int sg  = seg[p];
    uint2 raw = ((const uint2*)g_hraw)[i];
    float2 f01 = __half22float2(*reinterpret_cast<const __half2*>(&raw.x));
    float2 f23 = __half22float2(*reinterpret_cast<const __half2*>(&raw.y));
    int tb = ((br * NINS + sg) << 6) + c4 * 4;
    float4 mm = *(const float4*)(g_mean + tb);
    float4 rr = *(const float4*)(g_rinv + tb);
    float x0 = fmaxf(0.f, (f01.x - mm.x) * rr.x);
    float x1 = fmaxf(0.f, (f01.y - mm.y) * rr.y);
    float x2 = fmaxf(0.f, (f23.x - mm.z) * rr.z);
    float x3 = fmaxf(0.f, (f23.y - mm.w) * rr.w);
    g_hn[i] = make_uint2(pack2(x0, x1), pack2(x2, x3));
}

// ---------------- final conv ----------------
__global__ void __launch_bounds__(256, 2) k_final_mma(
    const int* __restrict__ idxs, const float* __restrict__ bf,
    float* __restrict__ out)
{
    extern __shared__ __half smh[];
    __half* sA   = smh;
    int*    snbr = (int*)(smh + 2 * SA_HALVES);

    int tid = threadIdx.x;
    int p0  = blockIdx.x * ROWS;

    for (int t = tid; t < ROWS * 9; t += 256) {
        int p = t / 9, k = t % 9;
        int gi = p0 + p;
        int b = idxs[3*gi], y = idxs[3*gi+1], x = idxs[3*gi+2];
        int ky = k / 3 - 1, kx = k % 3 - 1;
        int ny = y + ky, nx = x + kx;
        int nbr = -1;
        if (ny >= 0 && ny < Hn && nx >= 0 && nx < Wn)
            nbr = g_idx_map[(b * Hn + ny) * Wn + nx];
        snbr[t] = nbr;
    }
    __syncthreads();

    int lane = tid & 31, wid = tid >> 5;
    int wm = wid >> 1, wn = wid & 1;
    int gid = lane >> 2, tig = lane & 3;
    int sub = lane >> 4, li = lane & 15;
    int lrow = lane & 15, lkh = lane >> 4;

    uint32_t sA_u = (uint32_t)__cvta_generic_to_shared(sA);

    float acc[4][4][4];
#pragma unroll
    for (int mi = 0; mi < 4; mi++)
#pragma unroll
        for (int ni = 0; ni < 4; ni++)
#pragma unroll
            for (int e = 0; e < 4; e++) acc[mi][ni][e] = 0.f;

    {
        uint32_t base = sA_u;
#pragma unroll
        for (int j = 0; j < 16; j++) {
            int row = wid * 32 + j * 2 + sub;
            int nbr = snbr[row * 9];
            cp_async8(base + row * 144 + li * 8,
                      g_ftH + (size_t)(nbr < 0 ? 0 : nbr) * 16 + li,
                      nbr >= 0 ? 8 : 0);
        }
        CP_COMMIT();
    }

    for (int u = 0; u < 36; u++) {
        if (u < 35) {
            int k2 = (u + 1) >> 2, c2 = (u + 1) & 3;
            const uint2* src2 = (c2 == 0) ? g_ftH : (g_hn + (size_t)(c2 - 1) * Np * 16);
            uint32_t base = sA_u + ((u + 1) & 1) * SA_BYTES;
#pragma unroll
            for (int j = 0; j < 16; j++) {
                int row = wid * 32 + j * 2 + sub;
                int nbr = snbr[row * 9 + k2];
                cp_async8(base + row * 144 + li * 8,
                          src2 + (size_t)(nbr < 0 ? 0 : nbr) * 16 + li,
                          nbr >= 0 ? 8 : 0);
            }
            CP_COMMIT();
            CP_WAIT1();
        } else {
            CP_WAIT0();
        }
        __syncthreads();

        uint32_t sAb_u = sA_u + (u & 1) * SA_BYTES;
        const uint2* wk = g_wtfH + u * 1024;
#pragma unroll
        for (int s = 0; s < 4; s++) {
            uint32_t a[4][4];
#pragma unroll
            for (int mi = 0; mi < 4; mi++) {
                uint32_t addr = sAb_u + (wm * 64 + mi * 16 + lrow) * 144 + s * 32 + lkh * 16;
                ldsm_x4(a[mi], addr);
            }
#pragma unroll
            for (int ni = 0; ni < 4; ni++) {
                uint2 bb = __ldg(wk + (s * 64 + wn * 32 + ni * 8 + gid) * 4 + tig);
#pragma unroll
                for (int mi = 0; mi < 4; mi++)
                    mma_f16(acc[mi][ni], a[mi][0], a[mi][1], a[mi][2], a[mi][3], bb.x, bb.y);
            }
        }
        __syncthreads();
    }

#pragma unroll
    for (int ni = 0; ni < 4; ni++) {
        int col = wn * 32 + ni * 8 + tig * 2;
        float2 bb = *(const float2*)(bf + col);
#pragma unroll
        for (int mi = 0; mi < 4; mi++) {
            int row = p0 + wm * 64 + mi * 16 + gid;
            float2 v0 = make_float2(acc[mi][ni][0] + bb.x, acc[mi][ni][1] + bb.y);
            float2 v1 = make_float2(acc[mi][ni][2] + bb.x, acc[mi][ni][3] + bb.y);
            *(float2*)(out + (size_t)row * 64 + col) = v0;
            *(float2*)(out + (size_t)(row + 8) * 64 + col) = v1;
        }
    }
}

// ---------------- launch ----------------
#define SMEM_CONV (2 * SA_BYTES + ROWS * 9 * 4)

extern "C" void kernel_launch(void* const* d_in, const int* in_sizes, int n_in,
                              void* d_out, int out_size)
{
    const float* feats = (const float*)d_in[0];
    const int*   idxs  = (const int*)  d_in[1];
    const int*   seg   = (const int*)  d_in[2];
    const float* w1    = (const float*)d_in[3];
    const float* b1    = (const float*)d_in[4];
    const float* w2    = (const float*)d_in[5];
    const float* b2    = (const float*)d_in[6];
    const float* w3    = (const float*)d_in[7];
    const float* b3    = (const float*)d_in[8];
    const float* wf    = (const float*)d_in[9];
    const float* bf    = (const float*)d_in[10];
    float* out = (float*)d_out;

    cudaFuncSetAttribute(k_branch_mma, cudaFuncAttributeMaxDynamicSharedMemorySize, SMEM_CONV);
    cudaFuncSetAttribute(k_final_mma,  cudaFuncAttributeMaxDynamicSharedMemorySize, SMEM_CONV);

    k_init<<<(Bn * Hn * Wn + 255) / 256, 256>>>();
    k_scatter<<<(Np + 255) / 256, 256>>>(idxs, seg);
    k_dil<<<1, 64>>>();
    k_prepw<<<(27648 + 36864 + 255) / 256, 256>>>(w1, w2, w3, wf);
    k_prepf<<<Np * 16 / 256, 256>>>(feats);

    dim3 gb(Np / ROWS, 3);
    k_branch_mma<<<gb, 256, SMEM_CONV>>>(idxs, seg, b1, b2, b3);

    k_normfin<<<12, 256>>>();
    k_hnorm<<<3 * Np * 16 / 256, 256>>>(seg);

    k_final_mma<<<Np / ROWS, 256, SMEM_CONV>>>(idxs, bf, out);
}

// round 14
// speedup vs baseline: 2.9003x; 1.0602x over previous
#include <cuda_runtime.h>
#include <cuda_fp16.h>
#include <cstdint>

#define Np   262144
#define Bn   4
#define Hn   512
#define Wn   512
#define NINS 16
#define EPSF 1e-5f

// ---------------- device scratch ----------------
__device__ int      g_idx_map[Bn * Hn * Wn];
__device__ __align__(16) uint32_t g_hraw[3u * Np * 32u];   // raw h fp16
__device__ __align__(16) uint2    g_hn[3u * Np * 16u];     // relu(norm(h)) fp16
__device__ __align__(16) uint2    g_ftH[Np * 16u];         // feats fp16
__device__ float g_sum [3 * NINS * 64];
__device__ float g_sum2[3 * NINS * 64];
__device__ float g_mean[3 * NINS * 64];
__device__ float g_rinv[3 * NINS * 64];
__device__ int   g_cnt [NINS];
__device__ int   g_ymin[NINS], g_ymax[NINS], g_xmin[NINS], g_xmax[NINS];
__device__ int   g_dil[3 * NINS];
__device__ uint2 g_wtbH[3 * 9 * 1024];
__device__ uint2 g_wtfH[36 * 1024];

// ---------------- helpers ----------------
__device__ __forceinline__ void mma_f16(float* d, uint32_t a0, uint32_t a1,
                                        uint32_t a2, uint32_t a3,
                                        uint32_t b0, uint32_t b1) {
    asm volatile(
        "mma.sync.aligned.m16n8k16.row.col.f32.f16.f16.f32 "
        "{%0,%1,%2,%3}, {%4,%5,%6,%7}, {%8,%9}, {%0,%1,%2,%3};"
        : "+f"(d[0]), "+f"(d[1]), "+f"(d[2]), "+f"(d[3])
        : "r"(a0), "r"(a1), "r"(a2), "r"(a3), "r"(b0), "r"(b1));
}

__device__ __forceinline__ void ldsm_x4(uint32_t* r, uint32_t addr) {
    asm volatile("ldmatrix.sync.aligned.m8n8.x4.shared.b16 {%0,%1,%2,%3}, [%4];"
                 : "=r"(r[0]), "=r"(r[1]), "=r"(r[2]), "=r"(r[3]) : "r"(addr));
}

__device__ __forceinline__ uint32_t pack2(float x, float y) {
    __half2 h = __floats2half2_rn(x, y);
    return *(uint32_t*)&h;
}

__device__ __forceinline__ void cp_async16(uint32_t dst, const void* src, int srcsize) {
    asm volatile("cp.async.ca.shared.global [%0], [%1], 16, %2;"
                 :: "r"(dst), "l"(src), "r"(srcsize) : "memory");
}
#define CP_COMMIT() asm volatile("cp.async.commit_group;" ::: "memory")
#define CP_WAIT1()  asm volatile("cp.async.wait_group 1;" ::: "memory")
#define CP_WAIT0()  asm volatile("cp.async.wait_group 0;" ::: "memory")

#define ROWS  256
#define SA_BYTES (ROWS * 144)

// ---------------- init / scatter / dil (proven) ----------------
__global__ void k_init() {
    int i = blockIdx.x * blockDim.x + threadIdx.x;
    if (i < Bn * Hn * Wn) g_idx_map[i] = -1;
    if (i < 3 * NINS * 64) { g_sum[i] = 0.f; g_sum2[i] = 0.f; }
    if (i < NINS) {
        g_cnt[i] = 0;
        g_ymin[i] = 0x7FFFFFFF; g_ymax[i] = 0x80000000;
        g_xmin[i] = 0x7FFFFFFF; g_xmax[i] = 0x80000000;
    }
}

__global__ void k_scatter(const int* __restrict__ idxs, const int* __restrict__ seg) {
    __shared__ int sy0[NINS], sy1[NINS], sx0[NINS], sx1[NINS], sc[NINS];
    int tid = threadIdx.x;
    if (tid < NINS) { sy0[tid] = 0x7FFFFFFF; sy1[tid] = 0x80000000;
                      sx0[tid] = 0x7FFFFFFF; sx1[tid] = 0x80000000; sc[tid] = 0; }
    __syncthreads();
    int i = blockIdx.x * blockDim.x + tid;
    if (i < Np) {
        int b = idxs[3*i], y = idxs[3*i+1], x = idxs[3*i+2];
        g_idx_map[(b * Hn + y) * Wn + x] = i;
        int s = seg[i];
        atomicMin(&sy0[s], y); atomicMax(&sy1[s], y);
        atomicMin(&sx0[s], x); atomicMax(&sx1[s], x);
        atomicAdd(&sc[s], 1);
    }
    __syncthreads();
    if (tid < NINS && sc[tid] > 0) {
        atomicMin(&g_ymin[tid], sy0[tid]); atomicMax(&g_ymax[tid], sy1[tid]);
        atomicMin(&g_xmin[tid], sx0[tid]); atomicMax(&g_xmax[tid], sx1[tid]);
        atomicAdd(&g_cnt[tid], sc[tid]);
    }
}

__global__ void k_dil() {
    int i = threadIdx.x;
    if (i < 3 * NINS) {
        int s = i & 15, r = i >> 4;
        int rate = (r == 0) ? 1 : (r == 1) ? 3 : 5;
        float hr = (float)(g_ymax[s] - g_ymin[s]) / (float)Hn;
        float wr = (float)(g_xmax[s] - g_xmin[s]) / (float)Wn;
        int d = (int)ceilf(fmaxf(hr, wr) * (float)rate);
        if (d < 1) d = 1;
        g_dil[r * NINS + s] = d;
    }
}

// ---------------- weight prep (proven) ----------------
__global__ void k_prepw(const float* __restrict__ w1, const float* __restrict__ w2,
                        const float* __restrict__ w3, const float* __restrict__ wf)
{
    int i = blockIdx.x * blockDim.x + threadIdx.x;
    if (i < 27648) {
        int br  = i / 9216;
        int r   = i % 9216;
        int tap = r / 1024;
        int r2  = r % 1024;
        int s   = r2 >> 8;
        int col = (r2 >> 2) & 63;
        int tig = r2 & 3;
        int kb  = s * 16 + tig * 2;
        const float* w = (br == 0) ? w1 : (br == 1) ? w2 : w3;
        const float* wt = w + tap * 4096;
        g_wtbH[i] = make_uint2(
            pack2(wt[(kb    ) * 64 + col], wt[(kb + 1) * 64 + col]),
            pack2(wt[(kb + 8) * 64 + col], wt[(kb + 9) * 64 + col]));
    } else if (i < 27648 + 36864) {
        int i2  = i - 27648;
        int u   = i2 / 1024;
        int r2  = i2 % 1024;
        int s   = r2 >> 8;
        int col = (r2 >> 2) & 63;
        int tig = r2 & 3;
        int tap = u >> 2, c = u & 3;
        int kb  = c * 64 + s * 16 + tig * 2;
        const float* wt = wf + (size_t)tap * 256 * 64;
        g_wtfH[i2] = make_uint2(
            pack2(wt[(kb    ) * 64 + col], wt[(kb + 1) * 64 + col]),
            pack2(wt[(kb + 8) * 64 + col], wt[(kb + 9) * 64 + col]));
    }
}

// ---------------- feats -> fp16 pre-convert ----------------
__global__ void __launch_bounds__(256) k_prepf(const float* __restrict__ feats) {
    int i = blockIdx.x * 256 + threadIdx.x;
    float4 f = ((const float4*)feats)[i];
    g_ftH[i] = make_uint2(pack2(f.x, f.y), pack2(f.z, f.w));
}

// ---------------- branch conv + fused stats: warp-autonomous mainloop ------
__global__ void __launch_bounds__(256, 2) k_branch_mma(
    const int* __restrict__ idxs, const int* __restrict__ seg,
    const float* __restrict__ bias1, const float* __restrict__ bias2,
    const float* __restrict__ bias3)
{
    extern __shared__ __half smh[];
    char* sA   = (char*)smh;                         // 2 x [256][144B]
    int*  snbr = (int*)(sA + 2 * SA_BYTES);          // 256*9

    int tid = threadIdx.x;
    int br  = blockIdx.y;
    int p0  = blockIdx.x * ROWS;
    const float* bias = (br == 0) ? bias1 : (br == 1) ? bias2 : bias3;

    for (int t = tid; t < ROWS * 9; t += 256) {
        int p = t / 9, k = t % 9;
        int gi = p0 + p;
        int b = idxs[3*gi], y = idxs[3*gi+1], x = idxs[3*gi+2];
        int sgi = seg[gi];
        int d = g_dil[br * NINS + sgi];
        int ky = k / 3 - 1, kx = k % 3 - 1;
        int ny = y + ky * d, nx = x + kx * d;
        int nbr = -1;
        if (ny >= 0 && ny < Hn && nx >= 0 && nx < Wn) {
            int n = g_idx_map[(b * Hn + ny) * Wn + nx];
            if (n >= 0 && seg[n] == sgi) nbr = n;
        }
        snbr[t] = nbr;
    }
    __syncthreads();

    int lane = tid & 31, wid = tid >> 5;
    int gid = lane >> 2, tig = lane & 3;
    int li8 = lane & 7, r4 = lane >> 3;       // fill: 8 lanes x 16B per row, 4 rows/instr
    int lrow = lane & 15, lkh = lane >> 4;    // ldmatrix

    uint32_t sA_u = (uint32_t)__cvta_generic_to_shared(sA);

    float acc[2][8][4];
#pragma unroll
    for (int mi = 0; mi < 2; mi++)
#pragma unroll
        for (int ni = 0; ni < 8; ni++)
#pragma unroll
            for (int e = 0; e < 4; e++) acc[mi][ni][e] = 0.f;

    const uint2* wtb = g_wtbH + (size_t)(br * 9) * 1024;

    // prefetch tap 0: warp fills its OWN 32 rows (8 instrs)
    {
#pragma unroll
        for (int j = 0; j < 8; j++) {
            int row = wid * 32 + j * 4 + r4;
            int nbr = snbr[row * 9];
            cp_async16(sA_u + row * 144 + li8 * 16,
                       (const char*)(g_ftH + (size_t)(nbr < 0 ? 0 : nbr) * 16) + li8 * 16,
                       nbr >= 0 ? 16 : 0);
        }
        CP_COMMIT();
    }

    for (int k = 0; k < 9; k++) {
        if (k < 8) {
            uint32_t base = sA_u + ((k + 1) & 1) * SA_BYTES;
#pragma unroll
            for (int j = 0; j < 8; j++) {
                int row = wid * 32 + j * 4 + r4;
                int nbr = snbr[row * 9 + k + 1];
                cp_async16(base + row * 144 + li8 * 16,
                           (const char*)(g_ftH + (size_t)(nbr < 0 ? 0 : nbr) * 16) + li8 * 16,
                           nbr >= 0 ? 16 : 0);
            }
            CP_COMMIT();
            CP_WAIT1();
        } else {
            CP_WAIT0();
        }
        __syncwarp();

        uint32_t sAb_u = sA_u + (k & 1) * SA_BYTES;
        const uint2* wk = wtb + k * 1024;
#pragma unroll
        for (int s = 0; s < 4; s++) {
            uint32_t a[2][4];
#pragma unroll
            for (int mi = 0; mi < 2; mi++) {
                uint32_t addr = sAb_u + (wid * 32 + mi * 16 + lrow) * 144 + s * 32 + lkh * 16;
                ldsm_x4(a[mi], addr);
            }
#pragma unroll
            for (int ni = 0; ni < 8; ni++) {
                uint2 bb = __ldg(wk + (s * 64 + ni * 8 + gid) * 4 + tig);
                mma_f16(acc[0][ni], a[0][0], a[0][1], a[0][2], a[0][3], bb.x, bb.y);
                mma_f16(acc[1][ni], a[1][0], a[1][1], a[1][2], a[1][3], bb.x, bb.y);
            }
        }
        __syncwarp();
    }

    // add bias, write raw h fp16
    uint32_t* hout = g_hraw + (size_t)br * Np * 32;
#pragma unroll
    for (int ni = 0; ni < 8; ni++) {
        int col = ni * 8 + tig * 2;
        float2 bb = *(const float2*)(bias + col);
#pragma unroll
        for (int mi = 0; mi < 2; mi++) {
            acc[mi][ni][0] += bb.x; acc[mi][ni][1] += bb.y;
            acc[mi][ni][2] += bb.x; acc[mi][ni][3] += bb.y;
            int row = p0 + wid * 32 + mi * 16 + gid;
            hout[(size_t)row * 32 + (col >> 1)] = pack2(acc[mi][ni][0], acc[mi][ni][1]);
            hout[(size_t)(row + 8) * 32 + (col >> 1)] = pack2(acc[mi][ni][2], acc[mi][ni][3]);
        }
    }

    // fused segment stats (per-warp 32-row span)
    int sg0 = seg[p0 + wid * 32], sg1 = seg[p0 + wid * 32 + 31];
    if (sg0 == sg1) {
#pragma unroll
        for (int ni = 0; ni < 8; ni++) {
            float s0 = acc[0][ni][0] + acc[0][ni][2] + acc[1][ni][0] + acc[1][ni][2];
            float s1 = acc[0][ni][1] + acc[0][ni][3] + acc[1][ni][1] + acc[1][ni][3];
            float q0 = acc[0][ni][0]*acc[0][ni][0] + acc[0][ni][2]*acc[0][ni][2]
                     + acc[1][ni][0]*acc[1][ni][0] + acc[1][ni][2]*acc[1][ni][2];
            float q1 = acc[0][ni][1]*acc[0][ni][1] + acc[0][ni][3]*acc[0][ni][3]
                     + acc[1][ni][1]*acc[1][ni][1] + acc[1][ni][3]*acc[1][ni][3];
#pragma unroll
            for (int m = 4; m < 32; m <<= 1) {
                s0 += __shfl_xor_sync(0xFFFFFFFF, s0, m);
                s1 += __shfl_xor_sync(0xFFFFFFFF, s1, m);
                q0 += __shfl_xor_sync(0xFFFFFFFF, q0, m);
                q1 += __shfl_xor_sync(0xFFFFFFFF, q1, m);
            }
            if (gid == 0) {
                int col = ni * 8 + tig * 2;
                int tb = (br * NINS + sg0) * 64 + col;
                atomicAdd(&g_sum [tb],     s0);
                atomicAdd(&g_sum [tb + 1], s1);
                atomicAdd(&g_sum2[tb],     q0);
                atomicAdd(&g_sum2[tb + 1], q1);
            }
        }
    } else {
#pragma unroll
        for (int ni = 0; ni < 8; ni++) {
            int col = ni * 8 + tig * 2;
#pragma unroll
            for (int mi = 0; mi < 2; mi++) {
                int rowa = p0 + wid * 32 + mi * 16 + gid;
                int rowb = rowa + 8;
                int sa = seg[rowa], sb = seg[rowb];
                int ta  = (br * NINS + sa) * 64 + col;
                int tb2 = (br * NINS + sb) * 64 + col;
                atomicAdd(&g_sum [ta],      acc[mi][ni][0]);
                atomicAdd(&g_sum [ta + 1],  acc[mi][ni][1]);
                atomicAdd(&g_sum2[ta],      acc[mi][ni][0]*acc[mi][ni][0]);
                atomicAdd(&g_sum2[ta + 1],  acc[mi][ni][1]*acc[mi][ni][1]);
                atomicAdd(&g_sum [tb2],     acc[mi][ni][2]);
                atomicAdd(&g_sum [tb2 + 1], acc[mi][ni][3]);
                atomicAdd(&g_sum2[tb2],     acc[mi][ni][2]*acc[mi][ni][2]);
                atomicAdd(&g_sum2[tb2 + 1], acc[mi][ni][3]*acc[mi][ni][3]);
            }
        }
    }
}

__global__ void k_normfin() {
    int i = blockIdx.x * blockDim.x + threadIdx.x;
    if (i < 3 * NINS * 64) {
        int sgl = (i / 64) % NINS;
        float cnt = (float)g_cnt[sgl];
        float mean = g_sum[i] / cnt;
        float var  = g_sum2[i] / cnt - mean * mean;
        g_mean[i] = mean;
        g_rinv[i] = rsqrtf(var + EPSF);
    }
}

// ---------------- normalize + relu (fp16 in/out) ----------------
__global__ void __launch_bounds__(256) k_hnorm(const int* __restrict__ seg) {
    int i = blockIdx.x * 256 + threadIdx.x;
    int br  = i / (Np * 16);
    int rem = i % (Np * 16);
    int p   = rem >> 4;
    int c4  = rem & 15;
    int sg  = seg[p];
    uint2 raw = ((const uint2*)g_hraw)[i];
    float2 f01 = __half22float2(*reinterpret_cast<const __half2*>(&raw.x));
    float2 f23 = __half22float2(*reinterpret_cast<const __half2*>(&raw.y));
    int tb = ((br * NINS + sg) << 6) + c4 * 4;
    float4 mm = *(const float4*)(g_mean + tb);
    float4 rr = *(const float4*)(g_rinv + tb);
    float x0 = fmaxf(0.f, (f01.x - mm.x) * rr.x);
    float x1 = fmaxf(0.f, (f01.y - mm.y) * rr.y);
    float x2 = fmaxf(0.f, (f23.x - mm.z) * rr.z);
    float x3 = fmaxf(0.f, (f23.y - mm.w) * rr.w);
    g_hn[i] = make_uint2(pack2(x0, x1), pack2(x2, x3));
}

// ---------------- final conv: warp-autonomous mainloop ----------------------
__global__ void __launch_bounds__(256, 2) k_final_mma(
    const int* __restrict__ idxs, const float* __restrict__ bf,
    float* __restrict__ out)
{
    extern __shared__ __half smh[];
    char* sA   = (char*)smh;
    int*  snbr = (int*)(sA + 2 * SA_BYTES);

    int tid = threadIdx.x;
    int p0  = blockIdx.x * ROWS;

    for (int t = tid; t < ROWS * 9; t += 256) {
        int p = t / 9, k = t % 9;
        int gi = p0 + p;
        int b = idxs[3*gi], y = idxs[3*gi+1], x = idxs[3*gi+2];
        int ky = k / 3 - 1, kx = k % 3 - 1;
        int ny = y + ky, nx = x + kx;
        int nbr = -1;
        if (ny >= 0 && ny < Hn && nx >= 0 && nx < Wn)
            nbr = g_idx_map[(b * Hn + ny) * Wn + nx];
        snbr[t] = nbr;
    }
    __syncthreads();

    int lane = tid & 31, wid = tid >> 5;
    int gid = lane >> 2, tig = lane & 3;
    int li8 = lane & 7, r4 = lane >> 3;
    int lrow = lane & 15, lkh = lane >> 4;

    uint32_t sA_u = (uint32_t)__cvta_generic_to_shared(sA);

    float acc[2][8][4];
#pragma unroll
    for (int mi = 0; mi < 2; mi++)
#pragma unroll
        for (int ni = 0; ni < 8; ni++)
#pragma unroll
            for (int e = 0; e < 4; e++) acc[mi][ni][e] = 0.f;

    {
#pragma unroll
        for (int j = 0; j < 8; j++) {
            int row = wid * 32 + j * 4 + r4;
            int nbr = snbr[row * 9];
            cp_async16(sA_u + row * 144 + li8 * 16,
                       (const char*)(g_ftH + (size_t)(nbr < 0 ? 0 : nbr) * 16) + li8 * 16,
                       nbr >= 0 ? 16 : 0);
        }
        CP_COMMIT();
    }

    for (int u = 0; u < 36; u++) {
        if (u < 35) {
            int k2 = (u + 1) >> 2, c2 = (u + 1) & 3;
            const uint2* src2 = (c2 == 0) ? g_ftH : (g_hn + (size_t)(c2 - 1) * Np * 16);
            uint32_t base = sA_u + ((u + 1) & 1) * SA_BYTES;
#pragma unroll
            for (int j = 0; j < 8; j++) {
                int row = wid * 32 + j * 4 + r4;
                int nbr = snbr[row * 9 + k2];
                cp_async16(base + row * 144 + li8 * 16,
                           (const char*)(src2 + (size_t)(nbr < 0 ? 0 : nbr) * 16) + li8 * 16,
                           nbr >= 0 ? 16 : 0);
            }
            CP_COMMIT();
            CP_WAIT1();
        } else {
            CP_WAIT0();
        }
        __syncwarp();

        uint32_t sAb_u = sA_u + (u & 1) * SA_BYTES;
        const uint2* wk = g_wtfH + u * 1024;
#pragma unroll
        for (int s = 0; s < 4; s++) {
            uint32_t a[2][4];
#pragma unroll
            for (int mi = 0; mi < 2; mi++) {
                uint32_t addr = sAb_u + (wid * 32 + mi * 16 + lrow) * 144 + s * 32 + lkh * 16;
                ldsm_x4(a[mi], addr);
            }
#pragma unroll
            for (int ni = 0; ni < 8; ni++) {
                uint2 bb = __ldg(wk + (s * 64 + ni * 8 + gid) * 4 + tig);
                mma_f16(acc[0][ni], a[0][0], a[0][1], a[0][2], a[0][3], bb.x, bb.y);
                mma_f16(acc[1][ni], a[1][0], a[1][1], a[1][2], a[1][3], bb.x, bb.y);
            }
        }
        __syncwarp();
    }

#pragma unroll
    for (int ni = 0; ni < 8; ni++) {
        int col = ni * 8 + tig * 2;
        float2 bb = *(const float2*)(bf + col);
#pragma unroll
        for (int mi = 0; mi < 2; mi++) {
            int row = p0 + wid * 32 + mi * 16 + gid;
            float2 v0 = make_float2(acc[mi][ni][0] + bb.x, acc[mi][ni][1] + bb.y);
            float2 v1 = make_float2(acc[mi][ni][2] + bb.x, acc[mi][ni][3] + bb.y);
            *(float2*)(out + (size_t)row * 64 + col) = v0;
            *(float2*)(out + (size_t)(row + 8) * 64 + col) = v1;
        }
    }
}

// ---------------- launch ----------------
#define SMEM_CONV (2 * SA_BYTES + ROWS * 9 * 4)

extern "C" void kernel_launch(void* const* d_in, const int* in_sizes, int n_in,
                              void* d_out, int out_size)
{
    const float* feats = (const float*)d_in[0];
    const int*   idxs  = (const int*)  d_in[1];
    const int*   seg   = (const int*)  d_in[2];
    const float* w1    = (const float*)d_in[3];
    const float* b1    = (const float*)d_in[4];
    const float* w2    = (const float*)d_in[5];
    const float* b2    = (const float*)d_in[6];
    const float* w3    = (const float*)d_in[7];
    const float* b3    = (const float*)d_in[8];
    const float* wf    = (const float*)d_in[9];
    const float* bf    = (const float*)d_in[10];
    float* out = (float*)d_out;

    cudaFuncSetAttribute(k_branch_mma, cudaFuncAttributeMaxDynamicSharedMemorySize, SMEM_CONV);
    cudaFuncSetAttribute(k_final_mma,  cudaFuncAttributeMaxDynamicSharedMemorySize, SMEM_CONV);

    k_init<<<(Bn * Hn * Wn + 255) / 256, 256>>>();
    k_scatter<<<(Np + 255) / 256, 256>>>(idxs, seg);
    k_dil<<<1, 64>>>();
    k_prepw<<<(27648 + 36864 + 255) / 256, 256>>>(w1, w2, w3, wf);
    k_prepf<<<Np * 16 / 256, 256>>>(feats);

    dim3 gb(Np / ROWS, 3);
    k_branch_mma<<<gb, 256, SMEM_CONV>>>(idxs, seg, b1, b2, b3);

    k_normfin<<<12, 256>>>();
    k_hnorm<<<3 * Np * 16 / 256, 256>>>(seg);

    k_final_mma<<<Np / ROWS, 256, SMEM_CONV>>>(idxs, bf, out);
}